// round 14
// baseline (speedup 1.0000x reference)
#include <cuda_runtime.h>
#include <cuda_bf16.h>
#include <math.h>
#include <stdint.h>

// Problem constants
#define Bq 512
#define Hh 512
#define Ll 64
#define Vv 1024
#define Tt 46
#define TBq 23552          // T*B
#define PADROW 23552
#define MSr 24064          // TB + B
#define MAXNB 8
#define NCMP 11776         // compacted pred rows (dirs==1)
#define MPRED 12288        // B + NCMP
#define NBLK 128           // persistent scan grid
#define STOPY 188          // MSr/128
#define PHIDY 92           // NCMP/128

// ---------------- scratch ----------------
__device__ float g_hbuf[(size_t)(TBq + 1) * Hh];
__device__ float g_hbufUr[(size_t)(TBq + 1) * Hh];
__device__ __nv_bfloat16 g_hbuf_hi[(size_t)(TBq + 1) * Hh];
__device__ __nv_bfloat16 g_hbuf_lo[(size_t)(TBq + 1) * Hh];
__device__ float g_Pz[(size_t)Vv * Hh];
__device__ float g_Pr[(size_t)Vv * Hh];
__device__ float g_Ph[(size_t)Vv * Hh];
__device__ float g_PembU[(size_t)Vv * Hh];
__device__ float g_PmolU[(size_t)Bq * Hh];
__device__ float g_PmolW[(size_t)Bq * Hh];
__device__ float g_sumh[(size_t)Bq * Hh];
__device__ __nv_bfloat16 g_curo_hi[(size_t)MSr * Hh];
__device__ __nv_bfloat16 g_curo_lo[(size_t)MSr * Hh];
__device__ __nv_bfloat16 g_phid_hi[(size_t)MPRED * Hh];
__device__ __nv_bfloat16 g_phid_lo[(size_t)MPRED * Hh];
__device__ float g_spart[(size_t)8 * MSr];
// softmax partials (16 col-slots per pred row)
__device__ float g_smax[(size_t)16 * MPRED];
__device__ float g_ssum[(size_t)16 * MPRED];
__device__ int   g_sargi[(size_t)16 * MPRED];
__device__ float g_tlog[MPRED];
__device__ int   g_cmap[NCMP + 256];
__device__ int   g_ccount;
__device__ int   g_barc;
__device__ double g_acc[5];
// scan split activations (per-step)
__device__ __nv_bfloat16 g_shg_hi[(size_t)2 * Bq * Hh];
__device__ __nv_bfloat16 g_shg_lo[(size_t)2 * Bq * Hh];
// bf16 split weights, stored [N, K]
__device__ __nv_bfloat16 g_Bu_hi[(size_t)Hh * Hh];
__device__ __nv_bfloat16 g_Bu_lo[(size_t)Hh * Hh];
__device__ __nv_bfloat16 g_Bw_hi[(size_t)Hh * Hh];
__device__ __nv_bfloat16 g_Bw_lo[(size_t)Hh * Hh];
__device__ __nv_bfloat16 g_Bo_hi[(size_t)Vv * Hh];
__device__ __nv_bfloat16 g_Bo_lo[(size_t)Vv * Hh];
__device__ __nv_bfloat16 g_Bzh_hi[(size_t)2 * Hh * Hh];
__device__ __nv_bfloat16 g_Bzh_lo[(size_t)2 * Hh * Hh];
__device__ __nv_bfloat16 g_BUr_hi[(size_t)Hh * Hh];
__device__ __nv_bfloat16 g_BUr_lo[(size_t)Hh * Hh];
__device__ __nv_bfloat16 g_Bz0_hi[(size_t)Hh * Hh];
__device__ __nv_bfloat16 g_Bz0_lo[(size_t)Hh * Hh];
__device__ __nv_bfloat16 g_Br0_hi[(size_t)Hh * Hh];
__device__ __nv_bfloat16 g_Br0_lo[(size_t)Hh * Hh];
__device__ __nv_bfloat16 g_Bh0_hi[(size_t)Hh * Hh];
__device__ __nv_bfloat16 g_Bh0_lo[(size_t)Hh * Hh];
__device__ __nv_bfloat16 g_BU0_hi[(size_t)Hh * Hh];
__device__ __nv_bfloat16 g_BU0_lo[(size_t)Hh * Hh];

// ---------------- helpers ----------------
__device__ __forceinline__ uint32_t smem_u32(const void* p) {
    uint32_t a;
    asm("{ .reg .u64 t; cvta.to.shared.u64 t, %1; cvt.u32.u64 %0, t; }"
        : "=r"(a) : "l"(p));
    return a;
}
__device__ __forceinline__ uint32_t lds32(uint32_t addr) {
    uint32_t v;
    asm volatile("ld.shared.b32 %0, [%1];" : "=r"(v) : "r"(addr));
    return v;
}
__device__ __forceinline__ void mma16816(float* d, const uint32_t* a,
                                         uint32_t b0, uint32_t b1) {
    asm volatile(
        "mma.sync.aligned.m16n8k16.row.col.f32.bf16.bf16.f32 "
        "{%0,%1,%2,%3}, {%4,%5,%6,%7}, {%8,%9}, {%0,%1,%2,%3};"
        : "+f"(d[0]), "+f"(d[1]), "+f"(d[2]), "+f"(d[3])
        : "r"(a[0]), "r"(a[1]), "r"(a[2]), "r"(a[3]), "r"(b0), "r"(b1));
}
__device__ __forceinline__ void splitbf(float v, __nv_bfloat16& h, __nv_bfloat16& l) {
    h = __float2bfloat16(v);
    l = __float2bfloat16(v - __bfloat162float(h));
}
__device__ __forceinline__ float fast_sigmoid(float x) {
    return __fdividef(1.f, 1.f + __expf(-x));
}
__device__ __forceinline__ float sigmoid_r(float x) {
    float t;
    asm("tanh.approx.f32 %0, %1;" : "=f"(t) : "f"(x * 0.5f));
    return fmaf(t, 0.5f, 0.5f);
}
__device__ __forceinline__ uint2 pack_hi4(float a, float b, float c, float d,
                                          uint2& lo_out) {
    __nv_bfloat16 h, l;
    __nv_bfloat162 h0, h1, l0, l1;
    splitbf(a, h, l); h0.x = h; l0.x = l;
    splitbf(b, h, l); h0.y = h; l0.y = l;
    splitbf(c, h, l); h1.x = h; l1.x = l;
    splitbf(d, h, l); h1.y = h; l1.y = l;
    lo_out.x = *(uint32_t*)&l0; lo_out.y = *(uint32_t*)&l1;
    uint2 r; r.x = *(uint32_t*)&h0; r.y = *(uint32_t*)&h1;
    return r;
}

// ---------------- light monotonic grid barrier ----------------
__device__ __forceinline__ void grid_bar(int nb, int& phase)
{
    __syncthreads();
    if (threadIdx.x == 0) {
        __threadfence();
        atomicAdd(&g_barc, 1);
        phase += nb;
        while (*(volatile int*)&g_barc < phase) { __nanosleep(16); }
        __threadfence();
    }
    __syncthreads();
}

// ---------------- generic 64x64 SGEMM (small precomputes) ----------------
#define BM 64
#define BN 64
#define BK 16

__global__ __launch_bounds__(256)
void sgemm_kernel(int M, int N, int K,
                  const float* __restrict__ A, const float* __restrict__ Bm,
                  const float* __restrict__ bias, float* __restrict__ C)
{
    __shared__ float As[BK][BM];
    __shared__ float Bs[BK][BN];
    const int tid = threadIdx.x;
    const int tx = tid & 15;
    const int ty = tid >> 4;
    const int m0 = blockIdx.y * BM;
    const int n0 = blockIdx.x * BN;

    const int a_row  = tid >> 2;
    const int a_col4 = (tid & 3) << 2;
    const int b_row  = tid >> 4;
    const int b_col4 = (tid & 15) << 2;

    const float* Aptr = A + (size_t)(m0 + a_row) * K + a_col4;
    const float* Bptr = Bm + (size_t)b_row * N + n0 + b_col4;

    float acc[4][4];
    #pragma unroll
    for (int i = 0; i < 4; i++)
        #pragma unroll
        for (int j = 0; j < 4; j++) acc[i][j] = 0.f;

    for (int k0 = 0; k0 < K; k0 += BK) {
        float4 av = *(const float4*)(Aptr + k0);
        float4 bv = *(const float4*)(Bptr + (size_t)k0 * N);
        As[a_col4 + 0][a_row] = av.x;
        As[a_col4 + 1][a_row] = av.y;
        As[a_col4 + 2][a_row] = av.z;
        As[a_col4 + 3][a_row] = av.w;
        *(float4*)&Bs[b_row][b_col4] = bv;
        __syncthreads();
        #pragma unroll
        for (int k = 0; k < BK; k++) {
            float4 a4 = *(const float4*)&As[k][ty << 2];
            float4 b4 = *(const float4*)&Bs[k][tx << 2];
            float a[4] = {a4.x, a4.y, a4.z, a4.w};
            float b[4] = {b4.x, b4.y, b4.z, b4.w};
            #pragma unroll
            for (int i = 0; i < 4; i++)
                #pragma unroll
                for (int j = 0; j < 4; j++) acc[i][j] = fmaf(a[i], b[j], acc[i][j]);
        }
        __syncthreads();
    }

    #pragma unroll
    for (int i = 0; i < 4; i++) {
        int row = m0 + (ty << 2) + i;
        int col = n0 + (tx << 2);
        float4 out;
        float b0 = bias ? bias[col + 0] : 0.f;
        float b1 = bias ? bias[col + 1] : 0.f;
        float b2 = bias ? bias[col + 2] : 0.f;
        float b3 = bias ? bias[col + 3] : 0.f;
        out.x = acc[i][0] + b0; out.y = acc[i][1] + b1;
        out.z = acc[i][2] + b2; out.w = acc[i][3] + b3;
        *(float4*)&C[(size_t)row * N + col] = out;
    }
}

// ---------------- batched weight transpose + bf16 split ----------------
struct ConvJob {
    const float* src;
    __nv_bfloat16* hi;
    __nv_bfloat16* lo;
    int nx;
};
struct ConvJobs { ConvJob j[10]; };

__global__ __launch_bounds__(256)
void convT_all(ConvJobs jobs)
{
    ConvJob jb = jobs.j[blockIdx.z];
    if ((int)blockIdx.x >= jb.nx) return;
    const int N = jb.nx * 32;
    const int K = Hh;
    __shared__ float t[32][33];
    int k0 = blockIdx.y * 32, n0 = blockIdx.x * 32;
    int tx = threadIdx.x & 31, ty = threadIdx.x >> 5;
    for (int r = ty; r < 32; r += 8)
        t[r][tx] = jb.src[(size_t)(k0 + r) * N + n0 + tx];
    __syncthreads();
    for (int r = ty; r < 32; r += 8) {
        float v = t[tx][r];
        __nv_bfloat16 h, l;
        splitbf(v, h, l);
        jb.hi[(size_t)(n0 + r) * K + k0 + tx] = h;
        jb.lo[(size_t)(n0 + r) * K + k0 + tx] = l;
    }
}

// ---------------- persistent fused GRU scan (double-buffered MMA) ----------------
#define SLDA 144
#define SA0 0
#define SA1 9216
#define SA2 18432
#define SA3 27648
#define SB0 36864
#define SB1 41472
#define SB2 46080
#define SB3 50688
#define HBUF 55296
#define SCAN_SMEM (2 * HBUF)

__global__ __launch_bounds__(256)
void scan_kernel(const int* __restrict__ wid, const int* __restrict__ hni)
{
    extern __shared__ char sms[];
    const uint32_t u0 = smem_u32(sms);
    __shared__ int s_ids4[4 * MAXNB];
    __shared__ int s_w4[4];

    const int tid = threadIdx.x;
    const int nb = (int)gridDim.x;
    const int wid_ = tid >> 5;
    const int lane = tid & 31;
    const int wm = wid_ & 3;
    const int wg = wid_ >> 2;
    const int qrow = lane >> 2;
    const int qk = (lane & 3) << 1;
    int barph = 0;

    for (int t = 0; t < Tt; t++) {
        // ---- P1: vectorized gather sum_h / sum_g (strided b's) ----
        {
            const int blk = (int)blockIdx.x;
            if (tid < 32)
                s_ids4[tid] = hni[((size_t)(t * Bq + blk + (tid >> 3) * NBLK)) * MAXNB + (tid & 7)];
            else if (tid < 36)
                s_w4[tid - 32] = wid[t * Bq + blk + (tid - 32) * NBLK];
            __syncthreads();
            #pragma unroll
            for (int it = 0; it < 2; it++) {
                int item = it * 256 + tid;
                int bl = item >> 7;
                int h4 = (item & 127) << 2;
                int b = blk + bl * NBLK;
                int w = s_w4[bl];
                float4 xr = *(const float4*)&g_Pr[(size_t)w * Hh + h4];
                float4 sh = {0.f, 0.f, 0.f, 0.f};
                float4 sg = {0.f, 0.f, 0.f, 0.f};
                #pragma unroll
                for (int n = 0; n < MAXNB; n++) {
                    int id = s_ids4[bl * 8 + n];
                    if (id == PADROW) continue;
                    float4 hv = *(const float4*)&g_hbuf[(size_t)id * Hh + h4];
                    float4 gv = *(const float4*)&g_hbufUr[(size_t)id * Hh + h4];
                    sh.x += hv.x; sh.y += hv.y; sh.z += hv.z; sh.w += hv.w;
                    sg.x += sigmoid_r(xr.x + gv.x) * hv.x;
                    sg.y += sigmoid_r(xr.y + gv.y) * hv.y;
                    sg.z += sigmoid_r(xr.z + gv.z) * hv.z;
                    sg.w += sigmoid_r(xr.w + gv.w) * hv.w;
                }
                *(float4*)&g_sumh[(size_t)b * Hh + h4] = sh;
                uint2 lo, hi;
                hi = pack_hi4(sh.x, sh.y, sh.z, sh.w, lo);
                *(uint2*)&g_shg_hi[(size_t)b * Hh + h4] = hi;
                *(uint2*)&g_shg_lo[(size_t)b * Hh + h4] = lo;
                hi = pack_hi4(sg.x, sg.y, sg.z, sg.w, lo);
                *(uint2*)&g_shg_hi[(size_t)(Bq + b) * Hh + h4] = hi;
                *(uint2*)&g_shg_lo[(size_t)(Bq + b) * Hh + h4] = lo;
            }
        }
        grid_bar(nb, barph);

        // ---- P2': dual 64x32 MMA (z & h_tilde), double-buffered ----
        {
            const int blk = (int)blockIdx.x;
            const int m0 = (blk >> 4) * 64;
            const int n0 = (blk & 15) * 32;

            float acc[4][4];
            #pragma unroll
            for (int nf = 0; nf < 4; nf++)
                #pragma unroll
                for (int r = 0; r < 4; r++) acc[nf][r] = 0.f;

            const int lr = tid >> 2, lq = tid & 3;
            const int rb = tid >> 3, qb = tid & 7;
            const char* gShH = (const char*)(g_shg_hi + (size_t)(m0 + lr) * Hh) + lq * 32;
            const char* gShL = (const char*)(g_shg_lo + (size_t)(m0 + lr) * Hh) + lq * 32;
            const char* gSgH = (const char*)(g_shg_hi + (size_t)(Bq + m0 + lr) * Hh) + lq * 32;
            const char* gSgL = (const char*)(g_shg_lo + (size_t)(Bq + m0 + lr) * Hh) + lq * 32;
            const char* gBzH = (const char*)(g_Bzh_hi + (size_t)(n0 + rb) * Hh) + qb * 16;
            const char* gBzL = (const char*)(g_Bzh_lo + (size_t)(n0 + rb) * Hh) + qb * 16;
            const char* gBtH = (const char*)(g_Bzh_hi + (size_t)(Hh + n0 + rb) * Hh) + qb * 16;
            const char* gBtL = (const char*)(g_Bzh_lo + (size_t)(Hh + n0 + rb) * Hh) + qb * 16;

            const uint32_t oAh = (wg ? SA2 : SA0);
            const uint32_t oAl = (wg ? SA3 : SA1);
            const uint32_t oBh = (wg ? SB2 : SB0);
            const uint32_t oBl = (wg ? SB3 : SB1);

            const float* P = wg ? g_Ph : g_Pz;
            const int rl0 = wm * 16 + qrow;
            const int row0 = m0 + rl0, row1 = row0 + 8;
            const int w0 = wid[t * Bq + row0], w1 = wid[t * Bq + row1];
            float2 pv0[4], pv1[4];
            #pragma unroll
            for (int nf = 0; nf < 4; nf++) {
                int col = n0 + nf * 8 + qk;
                pv0[nf] = *(const float2*)&P[(size_t)w0 * Hh + col];
                pv1[nf] = *(const float2*)&P[(size_t)w1 * Hh + col];
            }

            {
                uint4 a0 = *(const uint4*)(gShH), a0b = *(const uint4*)(gShH + 16);
                uint4 a1 = *(const uint4*)(gShL), a1b = *(const uint4*)(gShL + 16);
                uint4 a2 = *(const uint4*)(gSgH), a2b = *(const uint4*)(gSgH + 16);
                uint4 a3 = *(const uint4*)(gSgL), a3b = *(const uint4*)(gSgL + 16);
                uint4 b0v = *(const uint4*)(gBzH), b1v = *(const uint4*)(gBzL);
                uint4 b2v = *(const uint4*)(gBtH), b3v = *(const uint4*)(gBtL);
                char* d;
                d = sms + SA0 + lr * SLDA + lq * 32; *(uint4*)d = a0; *(uint4*)(d + 16) = a0b;
                d = sms + SA1 + lr * SLDA + lq * 32; *(uint4*)d = a1; *(uint4*)(d + 16) = a1b;
                d = sms + SA2 + lr * SLDA + lq * 32; *(uint4*)d = a2; *(uint4*)(d + 16) = a2b;
                d = sms + SA3 + lr * SLDA + lq * 32; *(uint4*)d = a3; *(uint4*)(d + 16) = a3b;
                *(uint4*)(sms + SB0 + rb * SLDA + qb * 16) = b0v;
                *(uint4*)(sms + SB1 + rb * SLDA + qb * 16) = b1v;
                *(uint4*)(sms + SB2 + rb * SLDA + qb * 16) = b2v;
                *(uint4*)(sms + SB3 + rb * SLDA + qb * 16) = b3v;
            }
            __syncthreads();

            #pragma unroll 1
            for (int c = 0; c < 8; c++) {
                const uint32_t ub = u0 + (c & 1) * HBUF;
                char* nxt = sms + ((c + 1) & 1) * HBUF;
                uint4 a0, a0b, a1, a1b, a2, a2b, a3, a3b, b0v, b1v, b2v, b3v;
                if (c < 7) {
                    int o = (c + 1) * 128;
                    a0 = *(const uint4*)(gShH + o); a0b = *(const uint4*)(gShH + o + 16);
                    a1 = *(const uint4*)(gShL + o); a1b = *(const uint4*)(gShL + o + 16);
                    a2 = *(const uint4*)(gSgH + o); a2b = *(const uint4*)(gSgH + o + 16);
                    a3 = *(const uint4*)(gSgL + o); a3b = *(const uint4*)(gSgL + o + 16);
                    b0v = *(const uint4*)(gBzH + o); b1v = *(const uint4*)(gBzL + o);
                    b2v = *(const uint4*)(gBtH + o); b3v = *(const uint4*)(gBtL + o);
                }
                #pragma unroll
                for (int kk = 0; kk < 4; kk++) {
                    const uint32_t koff = (kk * 16 + qk) * 2;
                    uint32_t base = (wm * 16 + qrow) * SLDA + koff;
                    uint32_t ah[4], al[4];
                    ah[0] = lds32(ub + oAh + base);
                    ah[1] = lds32(ub + oAh + base + 8 * SLDA);
                    ah[2] = lds32(ub + oAh + base + 16);
                    ah[3] = lds32(ub + oAh + base + 8 * SLDA + 16);
                    al[0] = lds32(ub + oAl + base);
                    al[1] = lds32(ub + oAl + base + 8 * SLDA);
                    al[2] = lds32(ub + oAl + base + 16);
                    al[3] = lds32(ub + oAl + base + 8 * SLDA + 16);
                    #pragma unroll
                    for (int nf = 0; nf < 4; nf++) {
                        uint32_t bb = (nf * 8 + qrow) * SLDA + koff;
                        uint32_t bh0 = lds32(ub + oBh + bb);
                        uint32_t bh1 = lds32(ub + oBh + bb + 16);
                        uint32_t cl0 = lds32(ub + oBl + bb);
                        uint32_t cl1 = lds32(ub + oBl + bb + 16);
                        mma16816(acc[nf], ah, bh0, bh1);
                        mma16816(acc[nf], ah, cl0, cl1);
                        mma16816(acc[nf], al, bh0, bh1);
                    }
                }
                if (c < 7) {
                    char* d;
                    d = nxt + SA0 + lr * SLDA + lq * 32; *(uint4*)d = a0; *(uint4*)(d + 16) = a0b;
                    d = nxt + SA1 + lr * SLDA + lq * 32; *(uint4*)d = a1; *(uint4*)(d + 16) = a1b;
                    d = nxt + SA2 + lr * SLDA + lq * 32; *(uint4*)d = a2; *(uint4*)(d + 16) = a2b;
                    d = nxt + SA3 + lr * SLDA + lq * 32; *(uint4*)d = a3; *(uint4*)(d + 16) = a3b;
                    *(uint4*)(nxt + SB0 + rb * SLDA + qb * 16) = b0v;
                    *(uint4*)(nxt + SB1 + rb * SLDA + qb * 16) = b1v;
                    *(uint4*)(nxt + SB2 + rb * SLDA + qb * 16) = b2v;
                    *(uint4*)(nxt + SB3 + rb * SLDA + qb * 16) = b3v;
                }
                __syncthreads();
            }

            float* xbuf = (float*)(sms + (wg ? 8192 : 0));
            #pragma unroll
            for (int nf = 0; nf < 4; nf++) {
                int cl = nf * 8 + qk;
                float v00 = acc[nf][0] + pv0[nf].x;
                float v01 = acc[nf][1] + pv0[nf].y;
                float v10 = acc[nf][2] + pv1[nf].x;
                float v11 = acc[nf][3] + pv1[nf].y;
                if (wg) {
                    v00 = tanhf(v00); v01 = tanhf(v01);
                    v10 = tanhf(v10); v11 = tanhf(v11);
                } else {
                    v00 = fast_sigmoid(v00); v01 = fast_sigmoid(v01);
                    v10 = fast_sigmoid(v10); v11 = fast_sigmoid(v11);
                }
                xbuf[rl0 * 32 + cl] = v00;
                xbuf[rl0 * 32 + cl + 1] = v01;
                xbuf[(rl0 + 8) * 32 + cl] = v10;
                xbuf[(rl0 + 8) * 32 + cl + 1] = v11;
            }
            __syncthreads();
            const float* zbuf = (const float*)(sms);
            const float* tbuf = (const float*)(sms + 8192);
            const size_t toff = (size_t)t * Bq * Hh;
            #pragma unroll
            for (int e = tid; e < 64 * 32; e += 256) {
                int rl = e >> 5, cl = e & 31;
                size_t gi = (size_t)(m0 + rl) * Hh + (n0 + cl);
                float z = zbuf[e], th = tbuf[e];
                float h = (1.f - z) * g_sumh[gi] + z * th;
                g_hbuf[toff + gi] = h;
                __nv_bfloat16 hi, lo;
                splitbf(h, hi, lo);
                g_hbuf_hi[toff + gi] = hi;
                g_hbuf_lo[toff + gi] = lo;
            }
        }
        grid_bar(nb, barph);

        // ---- P4: hbufUr[t] = h_new @ Ur (64x32 tile, double-buffered) ----
        {
            const int blk = (int)blockIdx.x;
            const int m0 = (blk >> 4) * 64;
            const int n0 = (blk & 15) * 32;
            const size_t toff = (size_t)t * Bq * Hh;

            float acc[2][4];
            #pragma unroll
            for (int nf = 0; nf < 2; nf++)
                #pragma unroll
                for (int r = 0; r < 4; r++) acc[nf][r] = 0.f;

            const int lr = tid >> 2, lq = tid & 3;
            const int br = tid >> 3, bq = tid & 7;
            const char* gAh = (const char*)(g_hbuf_hi + toff + (size_t)(m0 + lr) * Hh) + lq * 32;
            const char* gAl = (const char*)(g_hbuf_lo + toff + (size_t)(m0 + lr) * Hh) + lq * 32;
            const char* gBh = (const char*)(g_BUr_hi + (size_t)(n0 + br) * Hh) + bq * 16;
            const char* gBl = (const char*)(g_BUr_lo + (size_t)(n0 + br) * Hh) + bq * 16;
            const int wn = wg;

            {
                uint4 ah0 = *(const uint4*)(gAh), ah1 = *(const uint4*)(gAh + 16);
                uint4 al0 = *(const uint4*)(gAl), al1 = *(const uint4*)(gAl + 16);
                uint4 bh0 = *(const uint4*)(gBh), bl0 = *(const uint4*)(gBl);
                char* d = sms + SA0 + lr * SLDA + lq * 32;
                *(uint4*)d = ah0; *(uint4*)(d + 16) = ah1;
                d = sms + SA1 + lr * SLDA + lq * 32;
                *(uint4*)d = al0; *(uint4*)(d + 16) = al1;
                *(uint4*)(sms + SB0 + br * SLDA + bq * 16) = bh0;
                *(uint4*)(sms + SB1 + br * SLDA + bq * 16) = bl0;
            }
            __syncthreads();

            #pragma unroll 1
            for (int c = 0; c < 8; c++) {
                const uint32_t ub = u0 + (c & 1) * HBUF;
                char* nxt = sms + ((c + 1) & 1) * HBUF;
                uint4 nah0, nah1, nal0, nal1, nbh0, nbl0;
                if (c < 7) {
                    int o = (c + 1) * 128;
                    nah0 = *(const uint4*)(gAh + o); nah1 = *(const uint4*)(gAh + o + 16);
                    nal0 = *(const uint4*)(gAl + o); nal1 = *(const uint4*)(gAl + o + 16);
                    nbh0 = *(const uint4*)(gBh + o); nbl0 = *(const uint4*)(gBl + o);
                }
                #pragma unroll
                for (int kk = 0; kk < 4; kk++) {
                    const uint32_t koff = (kk * 16 + qk) * 2;
                    uint32_t base = (wm * 16 + qrow) * SLDA + koff;
                    uint32_t ah[4], al[4];
                    ah[0] = lds32(ub + SA0 + base);
                    ah[1] = lds32(ub + SA0 + base + 8 * SLDA);
                    ah[2] = lds32(ub + SA0 + base + 16);
                    ah[3] = lds32(ub + SA0 + base + 8 * SLDA + 16);
                    al[0] = lds32(ub + SA1 + base);
                    al[1] = lds32(ub + SA1 + base + 8 * SLDA);
                    al[2] = lds32(ub + SA1 + base + 16);
                    al[3] = lds32(ub + SA1 + base + 8 * SLDA + 16);
                    #pragma unroll
                    for (int nf = 0; nf < 2; nf++) {
                        uint32_t bb = (wn * 16 + nf * 8 + qrow) * SLDA + koff;
                        uint32_t b0 = lds32(ub + SB0 + bb);
                        uint32_t b1 = lds32(ub + SB0 + bb + 16);
                        uint32_t c0 = lds32(ub + SB1 + bb);
                        uint32_t c1 = lds32(ub + SB1 + bb + 16);
                        mma16816(acc[nf], ah, b0, b1);
                        mma16816(acc[nf], ah, c0, c1);
                        mma16816(acc[nf], al, b0, b1);
                    }
                }
                if (c < 7) {
                    char* d = nxt + SA0 + lr * SLDA + lq * 32;
                    *(uint4*)d = nah0; *(uint4*)(d + 16) = nah1;
                    d = nxt + SA1 + lr * SLDA + lq * 32;
                    *(uint4*)d = nal0; *(uint4*)(d + 16) = nal1;
                    *(uint4*)(nxt + SB0 + br * SLDA + bq * 16) = nbh0;
                    *(uint4*)(nxt + SB1 + br * SLDA + bq * 16) = nbl0;
                }
                __syncthreads();
            }
            float* Cc = g_hbufUr + toff;
            int r0 = m0 + wm * 16 + qrow;
            #pragma unroll
            for (int nf = 0; nf < 2; nf++) {
                int col = n0 + wn * 16 + nf * 8 + qk;
                float2 o0 = {acc[nf][0], acc[nf][1]};
                float2 o1 = {acc[nf][2], acc[nf][3]};
                *(float2*)&Cc[(size_t)r0 * Hh + col] = o0;
                *(float2*)&Cc[(size_t)(r0 + 8) * Hh + col] = o1;
            }
        }
        grid_bar(nb, barph);
    }
}

// ---------------- tc mainloops (double-buffered) ----------------
#define LDA_B 144
#define OFF_ALO 18432
#define OFF_BHI 36864
#define OFF_BLO 55296
#define TCBUF 73728
#define TCSM_BYTES (2 * TCBUF)

// fp32-A mainloop (emb precompute only), double-buffered
__device__ __forceinline__ void tc_main(
    const float* Abase, const char* BhiBase, const char* BloBase,
    char* smc, uint32_t sbase, int tid, int wm, int wn, int qrow, int qk,
    float acc[2][8][4])
{
    const int ar = tid >> 1;
    const int ac = (tid & 1) * 32;
    const int bo = (tid & 1) * 64;

    // chunk 0: load + convert + store into buf0
    {
        float4 av[8];
        uint4 bh[4], bl[4];
        #pragma unroll
        for (int f = 0; f < 8; f++) av[f] = *(const float4*)(Abase + f * 4);
        #pragma unroll
        for (int u = 0; u < 4; u++) {
            bh[u] = *(const uint4*)(BhiBase + u * 16);
            bl[u] = *(const uint4*)(BloBase + u * 16);
        }
        char* sa = smc + ar * LDA_B + ac * 2;
        char* sl = sa + OFF_ALO;
        #pragma unroll
        for (int f = 0; f < 8; f++) {
            __nv_bfloat16 h0, h1, h2, h3, l0, l1, l2, l3;
            splitbf(av[f].x, h0, l0);
            splitbf(av[f].y, h1, l1);
            splitbf(av[f].z, h2, l2);
            splitbf(av[f].w, h3, l3);
            __nv_bfloat162 hh0, hh1, ll0, ll1;
            hh0.x = h0; hh0.y = h1; hh1.x = h2; hh1.y = h3;
            ll0.x = l0; ll0.y = l1; ll1.x = l2; ll1.y = l3;
            uint2 hv = {*(uint32_t*)&hh0, *(uint32_t*)&hh1};
            uint2 lv = {*(uint32_t*)&ll0, *(uint32_t*)&ll1};
            *(uint2*)(sa + f * 8) = hv;
            *(uint2*)(sl + f * 8) = lv;
        }
        char* sb = smc + OFF_BHI + ar * LDA_B + bo;
        char* sbl = smc + OFF_BLO + ar * LDA_B + bo;
        #pragma unroll
        for (int u = 0; u < 4; u++) {
            *(uint4*)(sb + u * 16) = bh[u];
            *(uint4*)(sbl + u * 16) = bl[u];
        }
    }
    __syncthreads();

    #pragma unroll 1
    for (int c = 0; c < 8; c++) {
        const uint32_t ub = sbase + (c & 1) * TCBUF;
        char* nbuf = smc + ((c + 1) & 1) * TCBUF;

        float4 nav[8];
        uint4 nbh[4], nbl[4];
        if (c < 7) {
            #pragma unroll
            for (int f = 0; f < 8; f++)
                nav[f] = *(const float4*)(Abase + (c + 1) * 64 + f * 4);
            #pragma unroll
            for (int u = 0; u < 4; u++) {
                nbh[u] = *(const uint4*)(BhiBase + (c + 1) * 128 + u * 16);
                nbl[u] = *(const uint4*)(BloBase + (c + 1) * 128 + u * 16);
            }
        }

        #pragma unroll
        for (int kk = 0; kk < 4; kk++) {
            const uint32_t koff = (kk * 16 + qk) * 2;
            uint32_t ah[2][4], al[2][4];
            #pragma unroll
            for (int mf = 0; mf < 2; mf++) {
                uint32_t base = ub + (wm * 32 + mf * 16 + qrow) * LDA_B + koff;
                ah[mf][0] = lds32(base);
                ah[mf][1] = lds32(base + 8 * LDA_B);
                ah[mf][2] = lds32(base + 16);
                ah[mf][3] = lds32(base + 8 * LDA_B + 16);
                al[mf][0] = lds32(base + OFF_ALO);
                al[mf][1] = lds32(base + OFF_ALO + 8 * LDA_B);
                al[mf][2] = lds32(base + OFF_ALO + 16);
                al[mf][3] = lds32(base + OFF_ALO + 8 * LDA_B + 16);
            }
            #pragma unroll
            for (int nf = 0; nf < 8; nf++) {
                uint32_t bb = ub + OFF_BHI + (wn * 64 + nf * 8 + qrow) * LDA_B + koff;
                uint32_t bh0 = lds32(bb);
                uint32_t bh1 = lds32(bb + 16);
                uint32_t bl0 = lds32(bb + (OFF_BLO - OFF_BHI));
                uint32_t bl1 = lds32(bb + (OFF_BLO - OFF_BHI) + 16);
                #pragma unroll
                for (int mf = 0; mf < 2; mf++) {
                    mma16816(acc[mf][nf], ah[mf], bh0, bh1);
                    mma16816(acc[mf][nf], ah[mf], bl0, bl1);
                    mma16816(acc[mf][nf], al[mf], bh0, bh1);
                }
            }
        }

        if (c < 7) {
            char* sa = nbuf + ar * LDA_B + ac * 2;
            char* sl = sa + OFF_ALO;
            #pragma unroll
            for (int f = 0; f < 8; f++) {
                __nv_bfloat16 h0, h1, h2, h3, l0, l1, l2, l3;
                splitbf(nav[f].x, h0, l0);
                splitbf(nav[f].y, h1, l1);
                splitbf(nav[f].z, h2, l2);
                splitbf(nav[f].w, h3, l3);
                __nv_bfloat162 hh0, hh1, ll0, ll1;
                hh0.x = h0; hh0.y = h1; hh1.x = h2; hh1.y = h3;
                ll0.x = l0; ll0.y = l1; ll1.x = l2; ll1.y = l3;
                uint2 hv = {*(uint32_t*)&hh0, *(uint32_t*)&hh1};
                uint2 lv = {*(uint32_t*)&ll0, *(uint32_t*)&ll1};
                *(uint2*)(sa + f * 8) = hv;
                *(uint2*)(sl + f * 8) = lv;
            }
            char* sb = nbuf + OFF_BHI + ar * LDA_B + bo;
            char* sbl = nbuf + OFF_BLO + ar * LDA_B + bo;
            #pragma unroll
            for (int u = 0; u < 4; u++) {
                *(uint4*)(sb + u * 16) = nbh[u];
                *(uint4*)(sbl + u * 16) = nbl[u];
            }
        }
        __syncthreads();
    }
}

// split-A mainloop (A already bf16 hi/lo), double-buffered
__device__ __forceinline__ void tc_main_sa(
    const char* AhiBase, const char* AloBase,
    const char* BhiBase, const char* BloBase,
    char* smc, uint32_t sbase, int tid, int wm, int wn, int qrow, int qk,
    float acc[2][8][4])
{
    const int ar = tid >> 1;
    const int bo = (tid & 1) * 64;
    const uint32_t rowoff = ar * LDA_B + bo;

    // chunk 0: load + store into buf0
    {
        uint4 xa[4], xl[4], xb[4], xc[4];
        #pragma unroll
        for (int u = 0; u < 4; u++) {
            xa[u] = *(const uint4*)(AhiBase + u * 16);
            xl[u] = *(const uint4*)(AloBase + u * 16);
            xb[u] = *(const uint4*)(BhiBase + u * 16);
            xc[u] = *(const uint4*)(BloBase + u * 16);
        }
        char* d = smc + rowoff;
        #pragma unroll
        for (int u = 0; u < 4; u++) {
            *(uint4*)(d + u * 16) = xa[u];
            *(uint4*)(d + OFF_ALO + u * 16) = xl[u];
            *(uint4*)(d + OFF_BHI + u * 16) = xb[u];
            *(uint4*)(d + OFF_BLO + u * 16) = xc[u];
        }
    }
    __syncthreads();

    #pragma unroll 1
    for (int c = 0; c < 8; c++) {
        const uint32_t ub = sbase + (c & 1) * TCBUF;
        char* nbuf = smc + ((c + 1) & 1) * TCBUF;

        uint4 na[4], nl[4], nb[4], nc[4];
        if (c < 7) {
            int o = (c + 1) * 128;
            #pragma unroll
            for (int u = 0; u < 4; u++) {
                na[u] = *(const uint4*)(AhiBase + o + u * 16);
                nl[u] = *(const uint4*)(AloBase + o + u * 16);
                nb[u] = *(const uint4*)(BhiBase + o + u * 16);
                nc[u] = *(const uint4*)(BloBase + o + u * 16);
            }
        }

        #pragma unroll
        for (int kk = 0; kk < 4; kk++) {
            const uint32_t koff = (kk * 16 + qk) * 2;
            uint32_t ah[2][4], al[2][4];
            #pragma unroll
            for (int mf = 0; mf < 2; mf++) {
                uint32_t base = ub + (wm * 32 + mf * 16 + qrow) * LDA_B + koff;
                ah[mf][0] = lds32(base);
                ah[mf][1] = lds32(base + 8 * LDA_B);
                ah[mf][2] = lds32(base + 16);
                ah[mf][3] = lds32(base + 8 * LDA_B + 16);
                al[mf][0] = lds32(base + OFF_ALO);
                al[mf][1] = lds32(base + OFF_ALO + 8 * LDA_B);
                al[mf][2] = lds32(base + OFF_ALO + 16);
                al[mf][3] = lds32(base + OFF_ALO + 8 * LDA_B + 16);
            }
            #pragma unroll
            for (int nf = 0; nf < 8; nf++) {
                uint32_t bb = ub + OFF_BHI + (wn * 64 + nf * 8 + qrow) * LDA_B + koff;
                uint32_t bh0 = lds32(bb);
                uint32_t bh1 = lds32(bb + 16);
                uint32_t bl0 = lds32(bb + (OFF_BLO - OFF_BHI));
                uint32_t bl1 = lds32(bb + (OFF_BLO - OFF_BHI) + 16);
                #pragma unroll
                for (int mf = 0; mf < 2; mf++) {
                    mma16816(acc[mf][nf], ah[mf], bh0, bh1);
                    mma16816(acc[mf][nf], ah[mf], bl0, bl1);
                    mma16816(acc[mf][nf], al[mf], bh0, bh1);
                }
            }
        }

        if (c < 7) {
            char* d = nbuf + rowoff;
            #pragma unroll
            for (int u = 0; u < 4; u++) {
                *(uint4*)(d + u * 16) = na[u];
                *(uint4*)(d + OFF_ALO + u * 16) = nl[u];
                *(uint4*)(d + OFF_BHI + u * 16) = nb[u];
                *(uint4*)(d + OFF_BLO + u * 16) = nc[u];
            }
        }
        __syncthreads();
    }
}

// merged post GEMM: blockIdx.y < STOPY -> stop head; else -> pred phid
__global__ __launch_bounds__(256)
void tc_gemm_post(const int* __restrict__ widp, const int* __restrict__ rootp,
                  const float* __restrict__ Us)
{
    extern __shared__ char smc[];
    const uint32_t sbase = smem_u32(smc);
    __shared__ int s_rows[128];

    const int tid = threadIdx.x;
    const int wid_ = tid >> 5;
    const int lane = tid & 31;
    const int wm = wid_ & 3;
    const int wn = wid_ >> 2;
    const int qrow = lane >> 2;
    const int qk = (lane & 3) << 1;
    const bool is_stop = (blockIdx.y < STOPY);
    const int m0 = (is_stop ? blockIdx.y : blockIdx.y - STOPY) * 128;
    const int n0 = blockIdx.x * 128;

    if (tid < 128) s_rows[tid] = is_stop ? (m0 + tid) : g_cmap[m0 + tid];
    __syncthreads();

    const int ar = tid >> 1;
    const int bo = (tid & 1) * 64;
    const __nv_bfloat16* Ahi = is_stop ? g_curo_hi : g_hbuf_hi;
    const __nv_bfloat16* Alo = is_stop ? g_curo_lo : g_hbuf_lo;
    const __nv_bfloat16* Bhi = is_stop ? g_Bu_hi : g_Bw_hi;
    const __nv_bfloat16* Blo = is_stop ? g_Bu_lo : g_Bw_lo;
    const char* AhiBase = (const char*)(Ahi + (size_t)s_rows[ar] * Hh) + bo;
    const char* AloBase = (const char*)(Alo + (size_t)s_rows[ar] * Hh) + bo;
    const char* BhiBase = (const char*)(Bhi + (size_t)(n0 + ar) * Hh) + bo;
    const char* BloBase = (const char*)(Blo + (size_t)(n0 + ar) * Hh) + bo;

    float acc[2][8][4];
    #pragma unroll
    for (int mf = 0; mf < 2; mf++)
        #pragma unroll
        for (int nf = 0; nf < 8; nf++)
            #pragma unroll
            for (int r = 0; r < 4; r++) acc[mf][nf][r] = 0.f;

    tc_main_sa(AhiBase, AloBase, BhiBase, BloBase, smc, sbase, tid, wm, wn, qrow, qk, acc);

    if (is_stop) {
        int slot = blockIdx.x * 2 + wn;
        #pragma unroll
        for (int mf = 0; mf < 2; mf++) {
            int r0 = m0 + wm * 32 + mf * 16 + qrow;
            int r1 = r0 + 8;
            int w0, b0, w1, b1;
            if (r0 < TBq) { w0 = widp[r0]; b0 = r0 & (Bq - 1); }
            else          { w0 = rootp[r0 - TBq]; b0 = r0 - TBq; }
            if (r1 < TBq) { w1 = widp[r1]; b1 = r1 & (Bq - 1); }
            else          { w1 = rootp[r1 - TBq]; b1 = r1 - TBq; }
            const float* Pe0 = g_PembU + (size_t)w0 * Hh;
            const float* Pm0 = g_PmolU + (size_t)b0 * Hh;
            const float* Pe1 = g_PembU + (size_t)w1 * Hh;
            const float* Pm1 = g_PmolU + (size_t)b1 * Hh;
            float p0 = 0.f, p1 = 0.f;
            #pragma unroll
            for (int nf = 0; nf < 8; nf++) {
                int col = wn * 64 + nf * 8 + qk;
                int gc = blockIdx.x * 128 + col;
                float u0 = Us[gc], u1 = Us[gc + 1];
                p0 += fmaxf(acc[mf][nf][0] + Pe0[gc] + Pm0[gc], 0.f) * u0;
                p0 += fmaxf(acc[mf][nf][1] + Pe0[gc + 1] + Pm0[gc + 1], 0.f) * u1;
                p1 += fmaxf(acc[mf][nf][2] + Pe1[gc] + Pm1[gc], 0.f) * u0;
                p1 += fmaxf(acc[mf][nf][3] + Pe1[gc + 1] + Pm1[gc + 1], 0.f) * u1;
            }
            p0 += __shfl_xor_sync(0xffffffffu, p0, 1);
            p0 += __shfl_xor_sync(0xffffffffu, p0, 2);
            p1 += __shfl_xor_sync(0xffffffffu, p1, 1);
            p1 += __shfl_xor_sync(0xffffffffu, p1, 2);
            if ((lane & 3) == 0) {
                g_spart[(size_t)slot * MSr + r0] = p0;
                g_spart[(size_t)slot * MSr + r1] = p1;
            }
        }
    } else {
        #pragma unroll
        for (int mf = 0; mf < 2; mf++) {
            int rl0 = wm * 32 + mf * 16 + qrow;
            int j0 = m0 + rl0;
            int bc0 = s_rows[rl0] & (Bq - 1);
            int bc1 = s_rows[rl0 + 8] & (Bq - 1);
            const float* Pm0 = g_PmolW + (size_t)bc0 * Hh;
            const float* Pm1 = g_PmolW + (size_t)bc1 * Hh;
            #pragma unroll
            for (int nf = 0; nf < 8; nf++) {
                int col = n0 + wn * 64 + nf * 8 + qk;
                float v00 = fmaxf(acc[mf][nf][0] + Pm0[col], 0.f);
                float v01 = fmaxf(acc[mf][nf][1] + Pm0[col + 1], 0.f);
                float v10 = fmaxf(acc[mf][nf][2] + Pm1[col], 0.f);
                float v11 = fmaxf(acc[mf][nf][3] + Pm1[col + 1], 0.f);
                __nv_bfloat162 h2, l2;
                __nv_bfloat16 h, l;
                splitbf(v00, h, l); h2.x = h; l2.x = l;
                splitbf(v01, h, l); h2.y = h; l2.y = l;
                *(__nv_bfloat162*)&g_phid_hi[(size_t)(Bq + j0) * Hh + col] = h2;
                *(__nv_bfloat162*)&g_phid_lo[(size_t)(Bq + j0) * Hh + col] = l2;
                splitbf(v10, h, l); h2.x = h; l2.x = l;
                splitbf(v11, h, l); h2.y = h; l2.y = l;
                *(__nv_bfloat162*)&g_phid_hi[(size_t)(Bq + j0 + 8) * Hh + col] = h2;
                *(__nv_bfloat162*)&g_phid_lo[(size_t)(Bq + j0 + 8) * Hh + col] = l2;
            }
        }
    }
}

// logits GEMM with fused softmax partials. grid (8, MPRED/128)
__global__ __launch_bounds__(256)
void tc_gemm_logits(const float* __restrict__ bias,
                    const int* __restrict__ root_wid, const int* __restrict__ y_wid)
{
    extern __shared__ char smc[];
    const uint32_t sbase = smem_u32(smc);

    const int tid = threadIdx.x;
    const int wid_ = tid >> 5;
    const int lane = tid & 31;
    const int wm = wid_ & 3;
    const int wn = wid_ >> 2;
    const int qrow = lane >> 2;
    const int qk = (lane & 3) << 1;
    const int m0 = blockIdx.y * 128;
    const int n0 = blockIdx.x * 128;

    const int ar = tid >> 1;
    const int bo = (tid & 1) * 64;
    const char* AhiBase = (const char*)(g_phid_hi + (size_t)(m0 + ar) * Hh) + bo;
    const char* AloBase = (const char*)(g_phid_lo + (size_t)(m0 + ar) * Hh) + bo;
    const char* BhiBase = (const char*)(g_Bo_hi + (size_t)(n0 + ar) * Hh) + bo;
    const char* BloBase = (const char*)(g_Bo_lo + (size_t)(n0 + ar) * Hh) + bo;

    float acc[2][8][4];
    #pragma unroll
    for (int mf = 0; mf < 2; mf++)
        #pragma unroll
        for (int nf = 0; nf < 8; nf++)
            #pragma unroll
            for (int r = 0; r < 4; r++) acc[mf][nf][r] = 0.f;

    tc_main_sa(AhiBase, AloBase, BhiBase, BloBase, smc, sbase, tid, wm, wn, qrow, qk, acc);

    const int slot = blockIdx.x * 2 + wn;
    #pragma unroll
    for (int mf = 0; mf < 2; mf++) {
        #pragma unroll
        for (int half = 0; half < 2; half++) {
            int j = m0 + wm * 32 + mf * 16 + qrow + half * 8;
            int tgt = (j < Bq) ? root_wid[j] : y_wid[g_cmap[j - Bq]];
            float mv = -1e30f; int mi = 0;
            float vv[16];
            #pragma unroll
            for (int nf = 0; nf < 8; nf++) {
                int col = n0 + wn * 64 + nf * 8 + qk;
                float a = acc[mf][nf][half * 2 + 0] + bias[col];
                float b = acc[mf][nf][half * 2 + 1] + bias[col + 1];
                vv[nf * 2] = a; vv[nf * 2 + 1] = b;
                if (a > mv) { mv = a; mi = col; }
                if (b > mv) { mv = b; mi = col + 1; }
                if (col == tgt) g_tlog[j] = a;
                if (col + 1 == tgt) g_tlog[j] = b;
            }
            #pragma unroll
            for (int o = 1; o <= 2; o <<= 1) {
                float ov = __shfl_xor_sync(0xffffffffu, mv, o);
                int oi = __shfl_xor_sync(0xffffffffu, mi, o);
                if (ov > mv || (ov == mv && oi < mi)) { mv = ov; mi = oi; }
            }
            float s = 0.f;
            #pragma unroll
            for (int k = 0; k < 16; k++) s += __expf(vv[k] - mv);
            s += __shfl_xor_sync(0xffffffffu, s, 1);
            s += __shfl_xor_sync(0xffffffffu, s, 2);
            if ((lane & 3) == 0) {
                g_smax[(size_t)slot * MPRED + j] = mv;
                g_ssum[(size_t)slot * MPRED + j] = s;
                g_sargi[(size_t)slot * MPRED + j] = mi;
            }
        }
    }
}

// fused emb-precompute: 4 GEMMs selected by blockIdx.z
__global__ __launch_bounds__(256)
void tc_gemm_pre4(const float* __restrict__ A,
                  const __nv_bfloat16* b0h, const __nv_bfloat16* b0l,
                  const float* bias0, float* C0,
                  const __nv_bfloat16* b1h, const __nv_bfloat16* b1l,
                  const float* bias1, float* C1,
                  const __nv_bfloat16* b2h, const __nv_bfloat16* b2l,
                  const float* bias2, float* C2,
                  const __nv_bfloat16* b3h, const __nv_bfloat16* b3l,
                  const float* bias3, float* C3)
{
    extern __shared__ char smc[];
    const uint32_t sbase = smem_u32(smc);
    const int z = blockIdx.z;
    const __nv_bfloat16* Bhi = (z == 0) ? b0h : (z == 1) ? b1h : (z == 2) ? b2h : b3h;
    const __nv_bfloat16* Blo = (z == 0) ? b0l : (z == 1) ? b1l : (z == 2) ? b2l : b3l;
    const float* bias = (z == 0) ? bias0 : (z == 1) ? bias1 : (z == 2) ? bias2 : bias3;
    float* C = (z == 0) ? C0 : (z == 1) ? C1 : (z == 2) ? C2 : C3;

    const int tid = threadIdx.x;
    const int wid_ = tid >> 5;
    const int lane = tid & 31;
    const int wm = wid_ & 3;
    const int wn = wid_ >> 2;
    const int qrow = lane >> 2;
    const int qk = (lane & 3) << 1;
    const int m0 = blockIdx.y * 128;
    const int n0 = blockIdx.x * 128;

    const int ar = tid >> 1;
    const int ac = (tid & 1) * 32;
    const int bo = (tid & 1) * 64;
    const float* Abase = A + (size_t)(m0 + ar) * Hh + ac;
    const char* BhiBase = (const char*)(Bhi + (size_t)(n0 + ar) * Hh) + bo;
    const char* BloBase = (const char*)(Blo + (size_t)(n0 + ar) * Hh) + bo;

    float acc[2][8][4];
    #pragma unroll
    for (int mf = 0; mf < 2; mf++)
        #pragma unroll
        for (int nf = 0; nf < 8; nf++)
            #pragma unroll
            for (int r = 0; r < 4; r++) acc[mf][nf][r] = 0.f;

    tc_main(Abase, BhiBase, BloBase, smc, sbase, tid, wm, wn, qrow, qk, acc);

    #pragma unroll
    for (int mf = 0; mf < 2; mf++) {
        int r0 = m0 + wm * 32 + mf * 16 + qrow;
        #pragma unroll
        for (int nf = 0; nf < 8; nf++) {
            int col = n0 + wn * 64 + nf * 8 + qk;
            float2 o0 = {acc[mf][nf][0] + bias[col], acc[mf][nf][1] + bias[col + 1]};
            float2 o1 = {acc[mf][nf][2] + bias[col], acc[mf][nf][3] + bias[col + 1]};
            *(float2*)&C[(size_t)r0 * Hh + col] = o0;
            *(float2*)&C[(size_t)(r0 + 8) * Hh + col] = o1;
        }
    }
}

// ---------------- housekeeping ----------------
__global__ __launch_bounds__(256)
void prep_kernel()
{
    int i = blockIdx.x * 256 + threadIdx.x;
    if (i < 5) g_acc[i] = 0.0;
    if (i == 5) { g_barc = 0; g_ccount = 0; }
    if (i < Hh) {
        g_hbuf[(size_t)PADROW * Hh + i] = 0.f;
        g_hbufUr[(size_t)PADROW * Hh + i] = 0.f;
        g_hbuf_hi[(size_t)PADROW * Hh + i] = __float2bfloat16(0.f);
        g_hbuf_lo[(size_t)PADROW * Hh + i] = __float2bfloat16(0.f);
    }
    if (i < NCMP + 256) g_cmap[i] = 0;
}

__global__ __launch_bounds__(256)
void compact_kernel(const int* __restrict__ dirs)
{
    int i = blockIdx.x * 256 + threadIdx.x;
    if (dirs[i]) {
        int s = atomicAdd(&g_ccount, 1);
        g_cmap[s] = i;
    }
}

// build_curo + phid0 merged (blocks >= MSr do phid0 rows)
__global__ __launch_bounds__(256)
void build_curo(const int* __restrict__ oni, const int* __restrict__ roni)
{
    int i = blockIdx.x, tid = threadIdx.x;
    if (i >= MSr) {
        int b = i - MSr;
        for (int h2 = tid * 2; h2 < Hh; h2 += 512) {
            float v0 = fmaxf(g_PmolW[(size_t)b * Hh + h2], 0.f);
            float v1 = fmaxf(g_PmolW[(size_t)b * Hh + h2 + 1], 0.f);
            __nv_bfloat162 h2v, l2v;
            __nv_bfloat16 h, l;
            splitbf(v0, h, l); h2v.x = h; l2v.x = l;
            splitbf(v1, h, l); h2v.y = h; l2v.y = l;
            *(__nv_bfloat162*)&g_phid_hi[(size_t)b * Hh + h2] = h2v;
            *(__nv_bfloat162*)&g_phid_lo[(size_t)b * Hh + h2] = l2v;
        }
        return;
    }
    __shared__ int ids[MAXNB];
    if (tid < MAXNB)
        ids[tid] = (i < TBq) ? oni[(size_t)i * MAXNB + tid]
                             : roni[(size_t)(i - TBq) * MAXNB + tid];
    __syncthreads();
    for (int h4 = tid * 4; h4 < Hh; h4 += 1024) {
        float4 v = {0.f, 0.f, 0.f, 0.f};
        #pragma unroll
        for (int n = 0; n < MAXNB; n++) {
            int id = ids[n];
            if (id == PADROW) continue;
            float4 hv = *(const float4*)&g_hbuf[(size_t)id * Hh + h4];
            v.x += hv.x; v.y += hv.y; v.z += hv.z; v.w += hv.w;
        }
        uint2 lo, hi;
        hi = pack_hi4(v.x, v.y, v.z, v.w, lo);
        *(uint2*)&g_curo_hi[(size_t)i * Hh + h4] = hi;
        *(uint2*)&g_curo_lo[(size_t)i * Hh + h4] = lo;
    }
}

// ---------------- stop head finalize ----------------
__global__ __launch_bounds__(256)
void stop_final_kernel(const float* __restrict__ bs, const int* __restrict__ dirs)
{
    int i = blockIdx.x * 256 + threadIdx.x;
    float s = bs[0];
    #pragma unroll
    for (int k = 0; k < 8; k++) s += g_spart[(size_t)k * MSr + i];
    float tgt = (i < TBq) ? (float)dirs[i] : 0.f;
    float loss = fmaxf(s, 0.f) - s * tgt + log1pf(expf(-fabsf(s)));
    float corr = ((s >= 0.5f) == (tgt > 0.5f)) ? 1.f : 0.f;
    __shared__ double r0[256], r1[256];
    int tid = threadIdx.x;
    r0[tid] = (double)loss;
    r1[tid] = (double)corr;
    __syncthreads();
    for (int o = 128; o > 0; o >>= 1) {
        if (tid < o) { r0[tid] += r0[tid + o]; r1[tid] += r1[tid + o]; }
        __syncthreads();
    }
    if (tid == 0) {
        atomicAdd(&g_acc[0], r0[0]);
        atomicAdd(&g_acc[1], r1[0]);
    }
}

// ---------------- pred finalize: combine softmax partials ----------------
__global__ __launch_bounds__(256)
void pred_final_kernel(const int* __restrict__ root_wid, const int* __restrict__ y_wid)
{
    int j = blockIdx.x * 256 + threadIdx.x;
    int tgt = (j < Bq) ? root_wid[j] : y_wid[g_cmap[j - Bq]];
    float gm = -1e30f; int gi = 0;
    #pragma unroll
    for (int s = 0; s < 16; s++) {
        float mv = g_smax[(size_t)s * MPRED + j];
        int mi = g_sargi[(size_t)s * MPRED + j];
        if (mv > gm) { gm = mv; gi = mi; }
    }
    float sum = 0.f;
    #pragma unroll
    for (int s = 0; s < 16; s++)
        sum += g_ssum[(size_t)s * MPRED + j] * __expf(g_smax[(size_t)s * MPRED + j] - gm);
    float lse = gm + logf(sum);
    float ce = -(g_tlog[j] - lse);
    float corr = (gi == tgt) ? 1.f : 0.f;

    __shared__ double r0[256], r1[256];
    int tid = threadIdx.x;
    r0[tid] = (double)ce;
    r1[tid] = (double)corr;
    __syncthreads();
    for (int o = 128; o > 0; o >>= 1) {
        if (tid < o) { r0[tid] += r0[tid + o]; r1[tid] += r1[tid + o]; }
        __syncthreads();
    }
    if (tid == 0) {
        atomicAdd(&g_acc[2], r0[0]);
        atomicAdd(&g_acc[3], r1[0]);
        atomicAdd(&g_acc[4], 256.0);
    }
}

__global__ void finalize_kernel(float* out)
{
    out[0] = (float)(g_acc[2] / (double)Bq);
    out[1] = (float)(g_acc[0] / (double)Bq);
    out[2] = (float)(g_acc[3] / g_acc[4]);
    out[3] = (float)(g_acc[1] / (double)MSr);
}

// ---------------- launch ----------------
extern "C" void kernel_launch(void* const* d_in, const int* in_sizes, int n_in,
                              void* d_out, int out_size)
{
    const float* mol_vec  = (const float*)d_in[0];
    const int*   wid      = (const int*)d_in[1];
    const int*   y_wid    = (const int*)d_in[2];
    const int*   dirs     = (const int*)d_in[3];
    const int*   hni      = (const int*)d_in[4];
    const int*   oni      = (const int*)d_in[5];
    const int*   root_wid = (const int*)d_in[6];
    const int*   roni     = (const int*)d_in[7];
    const float* emb      = (const float*)d_in[8];
    const float* Wz       = (const float*)d_in[9];
    const float* bz       = (const float*)d_in[10];
    const float* Wr       = (const float*)d_in[11];
    const float* br       = (const float*)d_in[12];
    const float* Ur       = (const float*)d_in[13];
    const float* Wh       = (const float*)d_in[14];
    const float* bh       = (const float*)d_in[15];
    const float* Wm       = (const float*)d_in[16];
    const float* bW       = (const float*)d_in[17];
    const float* U        = (const float*)d_in[18];
    const float* bU       = (const float*)d_in[19];
    const float* Wo       = (const float*)d_in[20];
    const float* bo       = (const float*)d_in[21];
    const float* Us       = (const float*)d_in[22];
    const float* bs       = (const float*)d_in[23];

    float *gPz, *gPr, *gPh, *gPembU, *gPmolU, *gPmolW;
    __nv_bfloat16 *gBuH, *gBuL, *gBwH, *gBwL, *gBoH, *gBoL;
    __nv_bfloat16 *gBzhH, *gBzhL, *gBUrH, *gBUrL;
    __nv_bfloat16 *gBz0H, *gBz0L, *gBr0H, *gBr0L, *gBh0H, *gBh0L, *gBU0H, *gBU0L;
    cudaGetSymbolAddress((void**)&gPz, g_Pz);
    cudaGetSymbolAddress((void**)&gPr, g_Pr);
    cudaGetSymbolAddress((void**)&gPh, g_Ph);
    cudaGetSymbolAddress((void**)&gPembU, g_PembU);
    cudaGetSymbolAddress((void**)&gPmolU, g_PmolU);
    cudaGetSymbolAddress((void**)&gPmolW, g_PmolW);
    cudaGetSymbolAddress((void**)&gBuH, g_Bu_hi);
    cudaGetSymbolAddress((void**)&gBuL, g_Bu_lo);
    cudaGetSymbolAddress((void**)&gBwH, g_Bw_hi);
    cudaGetSymbolAddress((void**)&gBwL, g_Bw_lo);
    cudaGetSymbolAddress((void**)&gBoH, g_Bo_hi);
    cudaGetSymbolAddress((void**)&gBoL, g_Bo_lo);
    cudaGetSymbolAddress((void**)&gBzhH, g_Bzh_hi);
    cudaGetSymbolAddress((void**)&gBzhL, g_Bzh_lo);
    cudaGetSymbolAddress((void**)&gBUrH, g_BUr_hi);
    cudaGetSymbolAddress((void**)&gBUrL, g_BUr_lo);
    cudaGetSymbolAddress((void**)&gBz0H, g_Bz0_hi);
    cudaGetSymbolAddress((void**)&gBz0L, g_Bz0_lo);
    cudaGetSymbolAddress((void**)&gBr0H, g_Br0_hi);
    cudaGetSymbolAddress((void**)&gBr0L, g_Br0_lo);
    cudaGetSymbolAddress((void**)&gBh0H, g_Bh0_hi);
    cudaGetSymbolAddress((void**)&gBh0L, g_Bh0_lo);
    cudaGetSymbolAddress((void**)&gBU0H, g_BU0_hi);
    cudaGetSymbolAddress((void**)&gBU0L, g_BU0_lo);

    cudaFuncSetAttribute(tc_gemm_post,
                         cudaFuncAttributeMaxDynamicSharedMemorySize, TCSM_BYTES);
    cudaFuncSetAttribute(tc_gemm_logits,
                         cudaFuncAttributeMaxDynamicSharedMemorySize, TCSM_BYTES);
    cudaFuncSetAttribute(tc_gemm_pre4,
                         cudaFuncAttributeMaxDynamicSharedMemorySize, TCSM_BYTES);
    cudaFuncSetAttribute(scan_kernel,
                         cudaFuncAttributeMaxDynamicSharedMemorySize, SCAN_SMEM);

    prep_kernel<<<47, 256>>>();
    compact_kernel<<<92, 256>>>(dirs);

    ConvJobs jobs;
    jobs.j[0] = {U + (size_t)Hh * Hh, gBuH, gBuL, 16};
    jobs.j[1] = {Wm, gBwH, gBwL, 16};
    jobs.j[2] = {Wo, gBoH, gBoL, 32};
    jobs.j[3] = {Wz + (size_t)Hh * Hh, gBzhH, gBzhL, 16};
    jobs.j[4] = {Wh + (size_t)Hh * Hh, gBzhH + (size_t)Hh * Hh, gBzhL + (size_t)Hh * Hh, 16};
    jobs.j[5] = {Ur, gBUrH, gBUrL, 16};
    jobs.j[6] = {Wz, gBz0H, gBz0L, 16};
    jobs.j[7] = {Wr, gBr0H, gBr0L, 16};
    jobs.j[8] = {Wh, gBh0H, gBh0L, 16};
    jobs.j[9] = {U, gBU0H, gBU0L, 16};
    convT_all<<<dim3(32, 16, 10), 256>>>(jobs);

    tc_gemm_pre4<<<dim3(4, 8, 4), 256, TCSM_BYTES>>>(
        emb,
        gBz0H, gBz0L, bz, gPz,
        gBr0H, gBr0L, br, gPr,
        gBh0H, gBh0L, bh, gPh,
        gBU0H, gBU0L, bU, gPembU);
    sgemm_kernel<<<dim3(Hh / BN, Bq / BM), 256>>>(Bq, Hh, Ll, mol_vec, U + (size_t)2 * Hh * Hh, nullptr, gPmolU);
    sgemm_kernel<<<dim3(Hh / BN, Bq / BM), 256>>>(Bq, Hh, Ll, mol_vec, Wm + (size_t)Hh * Hh, bW, gPmolW);

    // persistent fused GRU scan
    scan_kernel<<<NBLK, 256, SCAN_SMEM>>>(wid, hni);

    // gathers (curo + phid rows 0..511)
    build_curo<<<MSr + Bq, 256>>>(oni, roni);

    // merged stop + phid GEMMs
    tc_gemm_post<<<dim3(4, STOPY + PHIDY), 256, TCSM_BYTES>>>(wid, root_wid, Us);
    stop_final_kernel<<<94, 256>>>(bs, dirs);

    // logits GEMM with fused softmax partials, then tiny finalize
    tc_gemm_logits<<<dim3(8, MPRED / 128), 256, TCSM_BYTES>>>(bo, root_wid, y_wid);
    pred_final_kernel<<<48, 256>>>(root_wid, y_wid);

    finalize_kernel<<<1, 1>>>((float*)d_out);
}

// round 15
// speedup vs baseline: 1.0797x; 1.0797x over previous
#include <cuda_runtime.h>
#include <cuda_bf16.h>
#include <math.h>
#include <stdint.h>

// Problem constants
#define Bq 512
#define Hh 512
#define Ll 64
#define Vv 1024
#define Tt 46
#define TBq 23552          // T*B
#define PADROW 23552
#define MSr 24064          // TB + B
#define MAXNB 8
#define NCMP 11776         // compacted pred rows (dirs==1)
#define MPRED 12288        // B + NCMP
#define NBLK 128           // persistent scan grid
#define STOPY 188          // MSr/128
#define PHIDY 92           // NCMP/128

// ---------------- scratch ----------------
__device__ float g_hbuf[(size_t)(TBq + 1) * Hh];
__device__ float g_hbufUr[(size_t)(TBq + 1) * Hh];
__device__ __nv_bfloat16 g_hbuf_hi[(size_t)(TBq + 1) * Hh];
__device__ __nv_bfloat16 g_hbuf_lo[(size_t)(TBq + 1) * Hh];
__device__ float g_Pz[(size_t)Vv * Hh];
__device__ float g_Pr[(size_t)Vv * Hh];
__device__ float g_Ph[(size_t)Vv * Hh];
__device__ float g_PembU[(size_t)Vv * Hh];
__device__ float g_PmolU[(size_t)Bq * Hh];
__device__ float g_PmolW[(size_t)Bq * Hh];
__device__ float g_sumh[(size_t)Bq * Hh];
__device__ __nv_bfloat16 g_curo_hi[(size_t)MSr * Hh];
__device__ __nv_bfloat16 g_curo_lo[(size_t)MSr * Hh];
__device__ __nv_bfloat16 g_phid_hi[(size_t)MPRED * Hh];
__device__ __nv_bfloat16 g_phid_lo[(size_t)MPRED * Hh];
__device__ float g_spart[(size_t)8 * MSr];
// softmax partials (16 col-slots per pred row)
__device__ float g_smax[(size_t)16 * MPRED];
__device__ float g_ssum[(size_t)16 * MPRED];
__device__ int   g_sargi[(size_t)16 * MPRED];
__device__ float g_tlog[MPRED];
__device__ int   g_cmap[NCMP + 256];
__device__ int   g_ccount;
__device__ int   g_barc;
__device__ double g_acc[5];
// scan split activations (per-step)
__device__ __nv_bfloat16 g_shg_hi[(size_t)2 * Bq * Hh];
__device__ __nv_bfloat16 g_shg_lo[(size_t)2 * Bq * Hh];
// bf16 split weights, stored [N, K]
__device__ __nv_bfloat16 g_Bu_hi[(size_t)Hh * Hh];
__device__ __nv_bfloat16 g_Bu_lo[(size_t)Hh * Hh];
__device__ __nv_bfloat16 g_Bw_hi[(size_t)Hh * Hh];
__device__ __nv_bfloat16 g_Bw_lo[(size_t)Hh * Hh];
__device__ __nv_bfloat16 g_Bo_hi[(size_t)Vv * Hh];
__device__ __nv_bfloat16 g_Bo_lo[(size_t)Vv * Hh];
__device__ __nv_bfloat16 g_Bzh_hi[(size_t)2 * Hh * Hh];
__device__ __nv_bfloat16 g_Bzh_lo[(size_t)2 * Hh * Hh];
__device__ __nv_bfloat16 g_BUr_hi[(size_t)Hh * Hh];
__device__ __nv_bfloat16 g_BUr_lo[(size_t)Hh * Hh];
__device__ __nv_bfloat16 g_Bz0_hi[(size_t)Hh * Hh];
__device__ __nv_bfloat16 g_Bz0_lo[(size_t)Hh * Hh];
__device__ __nv_bfloat16 g_Br0_hi[(size_t)Hh * Hh];
__device__ __nv_bfloat16 g_Br0_lo[(size_t)Hh * Hh];
__device__ __nv_bfloat16 g_Bh0_hi[(size_t)Hh * Hh];
__device__ __nv_bfloat16 g_Bh0_lo[(size_t)Hh * Hh];
__device__ __nv_bfloat16 g_BU0_hi[(size_t)Hh * Hh];
__device__ __nv_bfloat16 g_BU0_lo[(size_t)Hh * Hh];

// ---------------- helpers ----------------
__device__ __forceinline__ uint32_t smem_u32(const void* p) {
    uint32_t a;
    asm("{ .reg .u64 t; cvta.to.shared.u64 t, %1; cvt.u32.u64 %0, t; }"
        : "=r"(a) : "l"(p));
    return a;
}
__device__ __forceinline__ uint32_t lds32(uint32_t addr) {
    uint32_t v;
    asm volatile("ld.shared.b32 %0, [%1];" : "=r"(v) : "r"(addr));
    return v;
}
__device__ __forceinline__ void mma16816(float* d, const uint32_t* a,
                                         uint32_t b0, uint32_t b1) {
    asm volatile(
        "mma.sync.aligned.m16n8k16.row.col.f32.bf16.bf16.f32 "
        "{%0,%1,%2,%3}, {%4,%5,%6,%7}, {%8,%9}, {%0,%1,%2,%3};"
        : "+f"(d[0]), "+f"(d[1]), "+f"(d[2]), "+f"(d[3])
        : "r"(a[0]), "r"(a[1]), "r"(a[2]), "r"(a[3]), "r"(b0), "r"(b1));
}
__device__ __forceinline__ void splitbf(float v, __nv_bfloat16& h, __nv_bfloat16& l) {
    h = __float2bfloat16(v);
    l = __float2bfloat16(v - __bfloat162float(h));
}
__device__ __forceinline__ float fast_sigmoid(float x) {
    return __fdividef(1.f, 1.f + __expf(-x));
}
__device__ __forceinline__ float sigmoid_r(float x) {
    float t;
    asm("tanh.approx.f32 %0, %1;" : "=f"(t) : "f"(x * 0.5f));
    return fmaf(t, 0.5f, 0.5f);
}
__device__ __forceinline__ uint2 pack_hi4(float a, float b, float c, float d,
                                          uint2& lo_out) {
    __nv_bfloat16 h, l;
    __nv_bfloat162 h0, h1, l0, l1;
    splitbf(a, h, l); h0.x = h; l0.x = l;
    splitbf(b, h, l); h0.y = h; l0.y = l;
    splitbf(c, h, l); h1.x = h; l1.x = l;
    splitbf(d, h, l); h1.y = h; l1.y = l;
    lo_out.x = *(uint32_t*)&l0; lo_out.y = *(uint32_t*)&l1;
    uint2 r; r.x = *(uint32_t*)&h0; r.y = *(uint32_t*)&h1;
    return r;
}

// ---------------- light monotonic grid barrier ----------------
__device__ __forceinline__ void grid_bar(int nb, int& phase)
{
    __syncthreads();
    if (threadIdx.x == 0) {
        __threadfence();
        atomicAdd(&g_barc, 1);
        phase += nb;
        while (*(volatile int*)&g_barc < phase) { __nanosleep(16); }
        __threadfence();
    }
    __syncthreads();
}

// ---------------- generic 64x64 SGEMM (small precomputes) ----------------
#define BM 64
#define BN 64
#define BK 16

__global__ __launch_bounds__(256)
void sgemm_kernel(int M, int N, int K,
                  const float* __restrict__ A, const float* __restrict__ Bm,
                  const float* __restrict__ bias, float* __restrict__ C)
{
    __shared__ float As[BK][BM];
    __shared__ float Bs[BK][BN];
    const int tid = threadIdx.x;
    const int tx = tid & 15;
    const int ty = tid >> 4;
    const int m0 = blockIdx.y * BM;
    const int n0 = blockIdx.x * BN;

    const int a_row  = tid >> 2;
    const int a_col4 = (tid & 3) << 2;
    const int b_row  = tid >> 4;
    const int b_col4 = (tid & 15) << 2;

    const float* Aptr = A + (size_t)(m0 + a_row) * K + a_col4;
    const float* Bptr = Bm + (size_t)b_row * N + n0 + b_col4;

    float acc[4][4];
    #pragma unroll
    for (int i = 0; i < 4; i++)
        #pragma unroll
        for (int j = 0; j < 4; j++) acc[i][j] = 0.f;

    for (int k0 = 0; k0 < K; k0 += BK) {
        float4 av = *(const float4*)(Aptr + k0);
        float4 bv = *(const float4*)(Bptr + (size_t)k0 * N);
        As[a_col4 + 0][a_row] = av.x;
        As[a_col4 + 1][a_row] = av.y;
        As[a_col4 + 2][a_row] = av.z;
        As[a_col4 + 3][a_row] = av.w;
        *(float4*)&Bs[b_row][b_col4] = bv;
        __syncthreads();
        #pragma unroll
        for (int k = 0; k < BK; k++) {
            float4 a4 = *(const float4*)&As[k][ty << 2];
            float4 b4 = *(const float4*)&Bs[k][tx << 2];
            float a[4] = {a4.x, a4.y, a4.z, a4.w};
            float b[4] = {b4.x, b4.y, b4.z, b4.w};
            #pragma unroll
            for (int i = 0; i < 4; i++)
                #pragma unroll
                for (int j = 0; j < 4; j++) acc[i][j] = fmaf(a[i], b[j], acc[i][j]);
        }
        __syncthreads();
    }

    #pragma unroll
    for (int i = 0; i < 4; i++) {
        int row = m0 + (ty << 2) + i;
        int col = n0 + (tx << 2);
        float4 out;
        float b0 = bias ? bias[col + 0] : 0.f;
        float b1 = bias ? bias[col + 1] : 0.f;
        float b2 = bias ? bias[col + 2] : 0.f;
        float b3 = bias ? bias[col + 3] : 0.f;
        out.x = acc[i][0] + b0; out.y = acc[i][1] + b1;
        out.z = acc[i][2] + b2; out.w = acc[i][3] + b3;
        *(float4*)&C[(size_t)row * N + col] = out;
    }
}

// ---------------- batched weight transpose + bf16 split ----------------
struct ConvJob {
    const float* src;
    __nv_bfloat16* hi;
    __nv_bfloat16* lo;
    int nx;
};
struct ConvJobs { ConvJob j[10]; };

__global__ __launch_bounds__(256)
void convT_all(ConvJobs jobs)
{
    ConvJob jb = jobs.j[blockIdx.z];
    if ((int)blockIdx.x >= jb.nx) return;
    const int N = jb.nx * 32;
    const int K = Hh;
    __shared__ float t[32][33];
    int k0 = blockIdx.y * 32, n0 = blockIdx.x * 32;
    int tx = threadIdx.x & 31, ty = threadIdx.x >> 5;
    for (int r = ty; r < 32; r += 8)
        t[r][tx] = jb.src[(size_t)(k0 + r) * N + n0 + tx];
    __syncthreads();
    for (int r = ty; r < 32; r += 8) {
        float v = t[tx][r];
        __nv_bfloat16 h, l;
        splitbf(v, h, l);
        jb.hi[(size_t)(n0 + r) * K + k0 + tx] = h;
        jb.lo[(size_t)(n0 + r) * K + k0 + tx] = l;
    }
}

// ---------------- persistent fused GRU scan (double-buffered MMA) ----------------
#define SLDA 144
#define SA0 0
#define SA1 9216
#define SA2 18432
#define SA3 27648
#define SB0 36864
#define SB1 41472
#define SB2 46080
#define SB3 50688
#define HBUF 55296
#define SCAN_SMEM (2 * HBUF)

__global__ __launch_bounds__(256)
void scan_kernel(const int* __restrict__ wid, const int* __restrict__ hni)
{
    extern __shared__ char sms[];
    const uint32_t u0 = smem_u32(sms);
    __shared__ int s_ids4[4 * MAXNB];
    __shared__ int s_w4[4];

    const int tid = threadIdx.x;
    const int nb = (int)gridDim.x;
    const int wid_ = tid >> 5;
    const int lane = tid & 31;
    const int wm = wid_ & 3;
    const int wg = wid_ >> 2;
    const int qrow = lane >> 2;
    const int qk = (lane & 3) << 1;
    int barph = 0;

    for (int t = 0; t < Tt; t++) {
        // ---- P1: vectorized gather sum_h / sum_g (strided b's) ----
        {
            const int blk = (int)blockIdx.x;
            if (tid < 32)
                s_ids4[tid] = hni[((size_t)(t * Bq + blk + (tid >> 3) * NBLK)) * MAXNB + (tid & 7)];
            else if (tid < 36)
                s_w4[tid - 32] = wid[t * Bq + blk + (tid - 32) * NBLK];
            __syncthreads();
            #pragma unroll
            for (int it = 0; it < 2; it++) {
                int item = it * 256 + tid;
                int bl = item >> 7;
                int h4 = (item & 127) << 2;
                int b = blk + bl * NBLK;
                int w = s_w4[bl];
                float4 xr = *(const float4*)&g_Pr[(size_t)w * Hh + h4];
                float4 sh = {0.f, 0.f, 0.f, 0.f};
                float4 sg = {0.f, 0.f, 0.f, 0.f};
                #pragma unroll
                for (int n = 0; n < MAXNB; n++) {
                    int id = s_ids4[bl * 8 + n];
                    if (id == PADROW) continue;
                    float4 hv = *(const float4*)&g_hbuf[(size_t)id * Hh + h4];
                    float4 gv = *(const float4*)&g_hbufUr[(size_t)id * Hh + h4];
                    sh.x += hv.x; sh.y += hv.y; sh.z += hv.z; sh.w += hv.w;
                    sg.x += sigmoid_r(xr.x + gv.x) * hv.x;
                    sg.y += sigmoid_r(xr.y + gv.y) * hv.y;
                    sg.z += sigmoid_r(xr.z + gv.z) * hv.z;
                    sg.w += sigmoid_r(xr.w + gv.w) * hv.w;
                }
                *(float4*)&g_sumh[(size_t)b * Hh + h4] = sh;
                uint2 lo, hi;
                hi = pack_hi4(sh.x, sh.y, sh.z, sh.w, lo);
                *(uint2*)&g_shg_hi[(size_t)b * Hh + h4] = hi;
                *(uint2*)&g_shg_lo[(size_t)b * Hh + h4] = lo;
                hi = pack_hi4(sg.x, sg.y, sg.z, sg.w, lo);
                *(uint2*)&g_shg_hi[(size_t)(Bq + b) * Hh + h4] = hi;
                *(uint2*)&g_shg_lo[(size_t)(Bq + b) * Hh + h4] = lo;
            }
        }
        grid_bar(nb, barph);

        // ---- P2': dual 64x32 MMA (z & h_tilde), double-buffered ----
        {
            const int blk = (int)blockIdx.x;
            const int m0 = (blk >> 4) * 64;
            const int n0 = (blk & 15) * 32;

            float acc[4][4];
            #pragma unroll
            for (int nf = 0; nf < 4; nf++)
                #pragma unroll
                for (int r = 0; r < 4; r++) acc[nf][r] = 0.f;

            const int lr = tid >> 2, lq = tid & 3;
            const int rb = tid >> 3, qb = tid & 7;
            const char* gShH = (const char*)(g_shg_hi + (size_t)(m0 + lr) * Hh) + lq * 32;
            const char* gShL = (const char*)(g_shg_lo + (size_t)(m0 + lr) * Hh) + lq * 32;
            const char* gSgH = (const char*)(g_shg_hi + (size_t)(Bq + m0 + lr) * Hh) + lq * 32;
            const char* gSgL = (const char*)(g_shg_lo + (size_t)(Bq + m0 + lr) * Hh) + lq * 32;
            const char* gBzH = (const char*)(g_Bzh_hi + (size_t)(n0 + rb) * Hh) + qb * 16;
            const char* gBzL = (const char*)(g_Bzh_lo + (size_t)(n0 + rb) * Hh) + qb * 16;
            const char* gBtH = (const char*)(g_Bzh_hi + (size_t)(Hh + n0 + rb) * Hh) + qb * 16;
            const char* gBtL = (const char*)(g_Bzh_lo + (size_t)(Hh + n0 + rb) * Hh) + qb * 16;

            const uint32_t oAh = (wg ? SA2 : SA0);
            const uint32_t oAl = (wg ? SA3 : SA1);
            const uint32_t oBh = (wg ? SB2 : SB0);
            const uint32_t oBl = (wg ? SB3 : SB1);

            const float* P = wg ? g_Ph : g_Pz;
            const int rl0 = wm * 16 + qrow;
            const int row0 = m0 + rl0, row1 = row0 + 8;
            const int w0 = wid[t * Bq + row0], w1 = wid[t * Bq + row1];
            float2 pv0[4], pv1[4];
            #pragma unroll
            for (int nf = 0; nf < 4; nf++) {
                int col = n0 + nf * 8 + qk;
                pv0[nf] = *(const float2*)&P[(size_t)w0 * Hh + col];
                pv1[nf] = *(const float2*)&P[(size_t)w1 * Hh + col];
            }
            // prefetch sumh for the h_new epilogue (hidden under mainloop)
            const size_t toff = (size_t)t * Bq * Hh;
            float sh8[8];
            #pragma unroll
            for (int e8 = 0; e8 < 8; e8++) {
                int e = e8 * 256 + tid;
                int rl = e >> 5, cl = e & 31;
                sh8[e8] = g_sumh[(size_t)(m0 + rl) * Hh + (n0 + cl)];
            }

            {
                uint4 a0 = *(const uint4*)(gShH), a0b = *(const uint4*)(gShH + 16);
                uint4 a1 = *(const uint4*)(gShL), a1b = *(const uint4*)(gShL + 16);
                uint4 a2 = *(const uint4*)(gSgH), a2b = *(const uint4*)(gSgH + 16);
                uint4 a3 = *(const uint4*)(gSgL), a3b = *(const uint4*)(gSgL + 16);
                uint4 b0v = *(const uint4*)(gBzH), b1v = *(const uint4*)(gBzL);
                uint4 b2v = *(const uint4*)(gBtH), b3v = *(const uint4*)(gBtL);
                char* d;
                d = sms + SA0 + lr * SLDA + lq * 32; *(uint4*)d = a0; *(uint4*)(d + 16) = a0b;
                d = sms + SA1 + lr * SLDA + lq * 32; *(uint4*)d = a1; *(uint4*)(d + 16) = a1b;
                d = sms + SA2 + lr * SLDA + lq * 32; *(uint4*)d = a2; *(uint4*)(d + 16) = a2b;
                d = sms + SA3 + lr * SLDA + lq * 32; *(uint4*)d = a3; *(uint4*)(d + 16) = a3b;
                *(uint4*)(sms + SB0 + rb * SLDA + qb * 16) = b0v;
                *(uint4*)(sms + SB1 + rb * SLDA + qb * 16) = b1v;
                *(uint4*)(sms + SB2 + rb * SLDA + qb * 16) = b2v;
                *(uint4*)(sms + SB3 + rb * SLDA + qb * 16) = b3v;
            }
            __syncthreads();

            #pragma unroll 1
            for (int c = 0; c < 8; c++) {
                const uint32_t ub = u0 + (c & 1) * HBUF;
                char* nxt = sms + ((c + 1) & 1) * HBUF;
                uint4 a0, a0b, a1, a1b, a2, a2b, a3, a3b, b0v, b1v, b2v, b3v;
                if (c < 7) {
                    int o = (c + 1) * 128;
                    a0 = *(const uint4*)(gShH + o); a0b = *(const uint4*)(gShH + o + 16);
                    a1 = *(const uint4*)(gShL + o); a1b = *(const uint4*)(gShL + o + 16);
                    a2 = *(const uint4*)(gSgH + o); a2b = *(const uint4*)(gSgH + o + 16);
                    a3 = *(const uint4*)(gSgL + o); a3b = *(const uint4*)(gSgL + o + 16);
                    b0v = *(const uint4*)(gBzH + o); b1v = *(const uint4*)(gBzL + o);
                    b2v = *(const uint4*)(gBtH + o); b3v = *(const uint4*)(gBtL + o);
                }
                #pragma unroll
                for (int kk = 0; kk < 4; kk++) {
                    const uint32_t koff = (kk * 16 + qk) * 2;
                    uint32_t base = (wm * 16 + qrow) * SLDA + koff;
                    uint32_t ah[4], al[4];
                    ah[0] = lds32(ub + oAh + base);
                    ah[1] = lds32(ub + oAh + base + 8 * SLDA);
                    ah[2] = lds32(ub + oAh + base + 16);
                    ah[3] = lds32(ub + oAh + base + 8 * SLDA + 16);
                    al[0] = lds32(ub + oAl + base);
                    al[1] = lds32(ub + oAl + base + 8 * SLDA);
                    al[2] = lds32(ub + oAl + base + 16);
                    al[3] = lds32(ub + oAl + base + 8 * SLDA + 16);
                    #pragma unroll
                    for (int nf = 0; nf < 4; nf++) {
                        uint32_t bb = (nf * 8 + qrow) * SLDA + koff;
                        uint32_t bh0 = lds32(ub + oBh + bb);
                        uint32_t bh1 = lds32(ub + oBh + bb + 16);
                        uint32_t cl0 = lds32(ub + oBl + bb);
                        uint32_t cl1 = lds32(ub + oBl + bb + 16);
                        mma16816(acc[nf], ah, bh0, bh1);
                        mma16816(acc[nf], ah, cl0, cl1);
                        mma16816(acc[nf], al, bh0, bh1);
                    }
                }
                if (c < 7) {
                    char* d;
                    d = nxt + SA0 + lr * SLDA + lq * 32; *(uint4*)d = a0; *(uint4*)(d + 16) = a0b;
                    d = nxt + SA1 + lr * SLDA + lq * 32; *(uint4*)d = a1; *(uint4*)(d + 16) = a1b;
                    d = nxt + SA2 + lr * SLDA + lq * 32; *(uint4*)d = a2; *(uint4*)(d + 16) = a2b;
                    d = nxt + SA3 + lr * SLDA + lq * 32; *(uint4*)d = a3; *(uint4*)(d + 16) = a3b;
                    *(uint4*)(nxt + SB0 + rb * SLDA + qb * 16) = b0v;
                    *(uint4*)(nxt + SB1 + rb * SLDA + qb * 16) = b1v;
                    *(uint4*)(nxt + SB2 + rb * SLDA + qb * 16) = b2v;
                    *(uint4*)(nxt + SB3 + rb * SLDA + qb * 16) = b3v;
                }
                __syncthreads();
            }

            float* xbuf = (float*)(sms + (wg ? 8192 : 0));
            #pragma unroll
            for (int nf = 0; nf < 4; nf++) {
                int cl = nf * 8 + qk;
                float v00 = acc[nf][0] + pv0[nf].x;
                float v01 = acc[nf][1] + pv0[nf].y;
                float v10 = acc[nf][2] + pv1[nf].x;
                float v11 = acc[nf][3] + pv1[nf].y;
                if (wg) {
                    v00 = tanhf(v00); v01 = tanhf(v01);
                    v10 = tanhf(v10); v11 = tanhf(v11);
                } else {
                    v00 = fast_sigmoid(v00); v01 = fast_sigmoid(v01);
                    v10 = fast_sigmoid(v10); v11 = fast_sigmoid(v11);
                }
                xbuf[rl0 * 32 + cl] = v00;
                xbuf[rl0 * 32 + cl + 1] = v01;
                xbuf[(rl0 + 8) * 32 + cl] = v10;
                xbuf[(rl0 + 8) * 32 + cl + 1] = v11;
            }
            __syncthreads();
            const float* zbuf = (const float*)(sms);
            const float* tbuf = (const float*)(sms + 8192);
            #pragma unroll
            for (int e8 = 0; e8 < 8; e8++) {
                int e = e8 * 256 + tid;
                int rl = e >> 5, cl = e & 31;
                size_t gi = (size_t)(m0 + rl) * Hh + (n0 + cl);
                float z = zbuf[e], th = tbuf[e];
                float h = (1.f - z) * sh8[e8] + z * th;
                g_hbuf[toff + gi] = h;
                __nv_bfloat16 hi, lo;
                splitbf(h, hi, lo);
                g_hbuf_hi[toff + gi] = hi;
                g_hbuf_lo[toff + gi] = lo;
            }
        }
        grid_bar(nb, barph);

        // ---- P4: hbufUr[t] = h_new @ Ur (64x32 tile, double-buffered) ----
        {
            const int blk = (int)blockIdx.x;
            const int m0 = (blk >> 4) * 64;
            const int n0 = (blk & 15) * 32;
            const size_t toff = (size_t)t * Bq * Hh;

            float acc[2][4];
            #pragma unroll
            for (int nf = 0; nf < 2; nf++)
                #pragma unroll
                for (int r = 0; r < 4; r++) acc[nf][r] = 0.f;

            const int lr = tid >> 2, lq = tid & 3;
            const int br = tid >> 3, bq = tid & 7;
            const char* gAh = (const char*)(g_hbuf_hi + toff + (size_t)(m0 + lr) * Hh) + lq * 32;
            const char* gAl = (const char*)(g_hbuf_lo + toff + (size_t)(m0 + lr) * Hh) + lq * 32;
            const char* gBh = (const char*)(g_BUr_hi + (size_t)(n0 + br) * Hh) + bq * 16;
            const char* gBl = (const char*)(g_BUr_lo + (size_t)(n0 + br) * Hh) + bq * 16;
            const int wn = wg;

            {
                uint4 ah0 = *(const uint4*)(gAh), ah1 = *(const uint4*)(gAh + 16);
                uint4 al0 = *(const uint4*)(gAl), al1 = *(const uint4*)(gAl + 16);
                uint4 bh0 = *(const uint4*)(gBh), bl0 = *(const uint4*)(gBl);
                char* d = sms + SA0 + lr * SLDA + lq * 32;
                *(uint4*)d = ah0; *(uint4*)(d + 16) = ah1;
                d = sms + SA1 + lr * SLDA + lq * 32;
                *(uint4*)d = al0; *(uint4*)(d + 16) = al1;
                *(uint4*)(sms + SB0 + br * SLDA + bq * 16) = bh0;
                *(uint4*)(sms + SB1 + br * SLDA + bq * 16) = bl0;
            }
            __syncthreads();

            #pragma unroll 1
            for (int c = 0; c < 8; c++) {
                const uint32_t ub = u0 + (c & 1) * HBUF;
                char* nxt = sms + ((c + 1) & 1) * HBUF;
                uint4 nah0, nah1, nal0, nal1, nbh0, nbl0;
                if (c < 7) {
                    int o = (c + 1) * 128;
                    nah0 = *(const uint4*)(gAh + o); nah1 = *(const uint4*)(gAh + o + 16);
                    nal0 = *(const uint4*)(gAl + o); nal1 = *(const uint4*)(gAl + o + 16);
                    nbh0 = *(const uint4*)(gBh + o); nbl0 = *(const uint4*)(gBl + o);
                }
                #pragma unroll
                for (int kk = 0; kk < 4; kk++) {
                    const uint32_t koff = (kk * 16 + qk) * 2;
                    uint32_t base = (wm * 16 + qrow) * SLDA + koff;
                    uint32_t ah[4], al[4];
                    ah[0] = lds32(ub + SA0 + base);
                    ah[1] = lds32(ub + SA0 + base + 8 * SLDA);
                    ah[2] = lds32(ub + SA0 + base + 16);
                    ah[3] = lds32(ub + SA0 + base + 8 * SLDA + 16);
                    al[0] = lds32(ub + SA1 + base);
                    al[1] = lds32(ub + SA1 + base + 8 * SLDA);
                    al[2] = lds32(ub + SA1 + base + 16);
                    al[3] = lds32(ub + SA1 + base + 8 * SLDA + 16);
                    #pragma unroll
                    for (int nf = 0; nf < 2; nf++) {
                        uint32_t bb = (wn * 16 + nf * 8 + qrow) * SLDA + koff;
                        uint32_t b0 = lds32(ub + SB0 + bb);
                        uint32_t b1 = lds32(ub + SB0 + bb + 16);
                        uint32_t c0 = lds32(ub + SB1 + bb);
                        uint32_t c1 = lds32(ub + SB1 + bb + 16);
                        mma16816(acc[nf], ah, b0, b1);
                        mma16816(acc[nf], ah, c0, c1);
                        mma16816(acc[nf], al, b0, b1);
                    }
                }
                if (c < 7) {
                    char* d = nxt + SA0 + lr * SLDA + lq * 32;
                    *(uint4*)d = nah0; *(uint4*)(d + 16) = nah1;
                    d = nxt + SA1 + lr * SLDA + lq * 32;
                    *(uint4*)d = nal0; *(uint4*)(d + 16) = nal1;
                    *(uint4*)(nxt + SB0 + br * SLDA + bq * 16) = nbh0;
                    *(uint4*)(nxt + SB1 + br * SLDA + bq * 16) = nbl0;
                }
                __syncthreads();
            }
            float* Cc = g_hbufUr + toff;
            int r0 = m0 + wm * 16 + qrow;
            #pragma unroll
            for (int nf = 0; nf < 2; nf++) {
                int col = n0 + wn * 16 + nf * 8 + qk;
                float2 o0 = {acc[nf][0], acc[nf][1]};
                float2 o1 = {acc[nf][2], acc[nf][3]};
                *(float2*)&Cc[(size_t)r0 * Hh + col] = o0;
                *(float2*)&Cc[(size_t)(r0 + 8) * Hh + col] = o1;
            }
        }
        grid_bar(nb, barph);
    }
}

// ---------------- tc mainloops (single-buffered, R13 layout) ----------------
#define LDA_B 144
#define OFF_ALO 18432
#define OFF_BHI 36864
#define OFF_BLO 55296
#define TCSM_BYTES 73728

// fp32-A mainloop (emb precompute only)
__device__ __forceinline__ void tc_main(
    const float* Abase, const char* BhiBase, const char* BloBase,
    char* smc, uint32_t sbase, int tid, int wm, int wn, int qrow, int qk,
    float acc[2][8][4])
{
    const int ar = tid >> 1;
    const int ac = (tid & 1) * 32;
    const int bo = (tid & 1) * 64;

    float4 av[8];
    uint4 bh[4], bl[4];
    #pragma unroll
    for (int f = 0; f < 8; f++) av[f] = *(const float4*)(Abase + f * 4);
    #pragma unroll
    for (int u = 0; u < 4; u++) {
        bh[u] = *(const uint4*)(BhiBase + u * 16);
        bl[u] = *(const uint4*)(BloBase + u * 16);
    }

    #pragma unroll 1
    for (int c = 0; c < 8; c++) {
        __syncthreads();
        {
            char* sa = smc + ar * LDA_B + ac * 2;
            char* sl = sa + OFF_ALO;
            #pragma unroll
            for (int f = 0; f < 8; f++) {
                __nv_bfloat16 h0, h1, h2, h3, l0, l1, l2, l3;
                splitbf(av[f].x, h0, l0);
                splitbf(av[f].y, h1, l1);
                splitbf(av[f].z, h2, l2);
                splitbf(av[f].w, h3, l3);
                __nv_bfloat162 hh0, hh1, ll0, ll1;
                hh0.x = h0; hh0.y = h1; hh1.x = h2; hh1.y = h3;
                ll0.x = l0; ll0.y = l1; ll1.x = l2; ll1.y = l3;
                uint2 hv = {*(uint32_t*)&hh0, *(uint32_t*)&hh1};
                uint2 lv = {*(uint32_t*)&ll0, *(uint32_t*)&ll1};
                *(uint2*)(sa + f * 8) = hv;
                *(uint2*)(sl + f * 8) = lv;
            }
            char* sb = smc + OFF_BHI + ar * LDA_B + bo;
            char* sbl = smc + OFF_BLO + ar * LDA_B + bo;
            #pragma unroll
            for (int u = 0; u < 4; u++) {
                *(uint4*)(sb + u * 16) = bh[u];
                *(uint4*)(sbl + u * 16) = bl[u];
            }
        }
        __syncthreads();

        float4 nav[8];
        uint4 nbh[4], nbl[4];
        if (c < 7) {
            #pragma unroll
            for (int f = 0; f < 8; f++)
                nav[f] = *(const float4*)(Abase + (c + 1) * 64 + f * 4);
            #pragma unroll
            for (int u = 0; u < 4; u++) {
                nbh[u] = *(const uint4*)(BhiBase + (c + 1) * 128 + u * 16);
                nbl[u] = *(const uint4*)(BloBase + (c + 1) * 128 + u * 16);
            }
        }

        #pragma unroll
        for (int kk = 0; kk < 4; kk++) {
            const uint32_t koff = (kk * 16 + qk) * 2;
            uint32_t ah[2][4], al[2][4];
            #pragma unroll
            for (int mf = 0; mf < 2; mf++) {
                uint32_t base = sbase + (wm * 32 + mf * 16 + qrow) * LDA_B + koff;
                ah[mf][0] = lds32(base);
                ah[mf][1] = lds32(base + 8 * LDA_B);
                ah[mf][2] = lds32(base + 16);
                ah[mf][3] = lds32(base + 8 * LDA_B + 16);
                al[mf][0] = lds32(base + OFF_ALO);
                al[mf][1] = lds32(base + OFF_ALO + 8 * LDA_B);
                al[mf][2] = lds32(base + OFF_ALO + 16);
                al[mf][3] = lds32(base + OFF_ALO + 8 * LDA_B + 16);
            }
            #pragma unroll
            for (int nf = 0; nf < 8; nf++) {
                uint32_t bb = sbase + OFF_BHI + (wn * 64 + nf * 8 + qrow) * LDA_B + koff;
                uint32_t bh0 = lds32(bb);
                uint32_t bh1 = lds32(bb + 16);
                uint32_t bl0 = lds32(bb + (OFF_BLO - OFF_BHI));
                uint32_t bl1 = lds32(bb + (OFF_BLO - OFF_BHI) + 16);
                #pragma unroll
                for (int mf = 0; mf < 2; mf++) {
                    mma16816(acc[mf][nf], ah[mf], bh0, bh1);
                    mma16816(acc[mf][nf], ah[mf], bl0, bl1);
                    mma16816(acc[mf][nf], al[mf], bh0, bh1);
                }
            }
        }
        if (c < 7) {
            #pragma unroll
            for (int f = 0; f < 8; f++) av[f] = nav[f];
            #pragma unroll
            for (int u = 0; u < 4; u++) { bh[u] = nbh[u]; bl[u] = nbl[u]; }
        }
    }
}

// split-A mainloop (A already bf16 hi/lo): pure copies + MMA
__device__ __forceinline__ void tc_main_sa(
    const char* AhiBase, const char* AloBase,
    const char* BhiBase, const char* BloBase,
    char* smc, uint32_t sbase, int tid, int wm, int wn, int qrow, int qk,
    float acc[2][8][4])
{
    const int ar = tid >> 1;
    const int bo = (tid & 1) * 64;

    uint4 xa[4], xl[4], xb[4], xc[4];
    #pragma unroll
    for (int u = 0; u < 4; u++) {
        xa[u] = *(const uint4*)(AhiBase + u * 16);
        xl[u] = *(const uint4*)(AloBase + u * 16);
        xb[u] = *(const uint4*)(BhiBase + u * 16);
        xc[u] = *(const uint4*)(BloBase + u * 16);
    }

    #pragma unroll 1
    for (int c = 0; c < 8; c++) {
        __syncthreads();
        {
            char* d = smc + ar * LDA_B + bo;
            #pragma unroll
            for (int u = 0; u < 4; u++) {
                *(uint4*)(d + u * 16) = xa[u];
                *(uint4*)(d + OFF_ALO + u * 16) = xl[u];
                *(uint4*)(d + OFF_BHI + u * 16) = xb[u];
                *(uint4*)(d + OFF_BLO + u * 16) = xc[u];
            }
        }
        __syncthreads();

        uint4 na[4], nl[4], nb[4], nc[4];
        if (c < 7) {
            int o = (c + 1) * 128;
            #pragma unroll
            for (int u = 0; u < 4; u++) {
                na[u] = *(const uint4*)(AhiBase + o + u * 16);
                nl[u] = *(const uint4*)(AloBase + o + u * 16);
                nb[u] = *(const uint4*)(BhiBase + o + u * 16);
                nc[u] = *(const uint4*)(BloBase + o + u * 16);
            }
        }

        #pragma unroll
        for (int kk = 0; kk < 4; kk++) {
            const uint32_t koff = (kk * 16 + qk) * 2;
            uint32_t ah[2][4], al[2][4];
            #pragma unroll
            for (int mf = 0; mf < 2; mf++) {
                uint32_t base = sbase + (wm * 32 + mf * 16 + qrow) * LDA_B + koff;
                ah[mf][0] = lds32(base);
                ah[mf][1] = lds32(base + 8 * LDA_B);
                ah[mf][2] = lds32(base + 16);
                ah[mf][3] = lds32(base + 8 * LDA_B + 16);
                al[mf][0] = lds32(base + OFF_ALO);
                al[mf][1] = lds32(base + OFF_ALO + 8 * LDA_B);
                al[mf][2] = lds32(base + OFF_ALO + 16);
                al[mf][3] = lds32(base + OFF_ALO + 8 * LDA_B + 16);
            }
            #pragma unroll
            for (int nf = 0; nf < 8; nf++) {
                uint32_t bb = sbase + OFF_BHI + (wn * 64 + nf * 8 + qrow) * LDA_B + koff;
                uint32_t bh0 = lds32(bb);
                uint32_t bh1 = lds32(bb + 16);
                uint32_t bl0 = lds32(bb + (OFF_BLO - OFF_BHI));
                uint32_t bl1 = lds32(bb + (OFF_BLO - OFF_BHI) + 16);
                #pragma unroll
                for (int mf = 0; mf < 2; mf++) {
                    mma16816(acc[mf][nf], ah[mf], bh0, bh1);
                    mma16816(acc[mf][nf], ah[mf], bl0, bl1);
                    mma16816(acc[mf][nf], al[mf], bh0, bh1);
                }
            }
        }
        if (c < 7) {
            #pragma unroll
            for (int u = 0; u < 4; u++) {
                xa[u] = na[u]; xl[u] = nl[u]; xb[u] = nb[u]; xc[u] = nc[u];
            }
        }
    }
}

// merged post GEMM: blockIdx.y < STOPY -> stop head; else -> pred phid
__global__ __launch_bounds__(256)
void tc_gemm_post(const int* __restrict__ widp, const int* __restrict__ rootp,
                  const float* __restrict__ Us)
{
    extern __shared__ char smc[];
    const uint32_t sbase = smem_u32(smc);
    __shared__ int s_rows[128];

    const int tid = threadIdx.x;
    const int wid_ = tid >> 5;
    const int lane = tid & 31;
    const int wm = wid_ & 3;
    const int wn = wid_ >> 2;
    const int qrow = lane >> 2;
    const int qk = (lane & 3) << 1;
    const bool is_stop = (blockIdx.y < STOPY);
    const int m0 = (is_stop ? blockIdx.y : blockIdx.y - STOPY) * 128;
    const int n0 = blockIdx.x * 128;

    if (tid < 128) s_rows[tid] = is_stop ? (m0 + tid) : g_cmap[m0 + tid];
    __syncthreads();

    const int ar = tid >> 1;
    const int bo = (tid & 1) * 64;
    const __nv_bfloat16* Ahi = is_stop ? g_curo_hi : g_hbuf_hi;
    const __nv_bfloat16* Alo = is_stop ? g_curo_lo : g_hbuf_lo;
    const __nv_bfloat16* Bhi = is_stop ? g_Bu_hi : g_Bw_hi;
    const __nv_bfloat16* Blo = is_stop ? g_Bu_lo : g_Bw_lo;
    const char* AhiBase = (const char*)(Ahi + (size_t)s_rows[ar] * Hh) + bo;
    const char* AloBase = (const char*)(Alo + (size_t)s_rows[ar] * Hh) + bo;
    const char* BhiBase = (const char*)(Bhi + (size_t)(n0 + ar) * Hh) + bo;
    const char* BloBase = (const char*)(Blo + (size_t)(n0 + ar) * Hh) + bo;

    float acc[2][8][4];
    #pragma unroll
    for (int mf = 0; mf < 2; mf++)
        #pragma unroll
        for (int nf = 0; nf < 8; nf++)
            #pragma unroll
            for (int r = 0; r < 4; r++) acc[mf][nf][r] = 0.f;

    tc_main_sa(AhiBase, AloBase, BhiBase, BloBase, smc, sbase, tid, wm, wn, qrow, qk, acc);

    if (is_stop) {
        int slot = blockIdx.x * 2 + wn;
        #pragma unroll
        for (int mf = 0; mf < 2; mf++) {
            int r0 = m0 + wm * 32 + mf * 16 + qrow;
            int r1 = r0 + 8;
            int w0, b0, w1, b1;
            if (r0 < TBq) { w0 = widp[r0]; b0 = r0 & (Bq - 1); }
            else          { w0 = rootp[r0 - TBq]; b0 = r0 - TBq; }
            if (r1 < TBq) { w1 = widp[r1]; b1 = r1 & (Bq - 1); }
            else          { w1 = rootp[r1 - TBq]; b1 = r1 - TBq; }
            const float* Pe0 = g_PembU + (size_t)w0 * Hh;
            const float* Pm0 = g_PmolU + (size_t)b0 * Hh;
            const float* Pe1 = g_PembU + (size_t)w1 * Hh;
            const float* Pm1 = g_PmolU + (size_t)b1 * Hh;
            float p0 = 0.f, p1 = 0.f;
            #pragma unroll
            for (int nf = 0; nf < 8; nf++) {
                int col = wn * 64 + nf * 8 + qk;
                int gc = blockIdx.x * 128 + col;
                float u0 = Us[gc], u1 = Us[gc + 1];
                p0 += fmaxf(acc[mf][nf][0] + Pe0[gc] + Pm0[gc], 0.f) * u0;
                p0 += fmaxf(acc[mf][nf][1] + Pe0[gc + 1] + Pm0[gc + 1], 0.f) * u1;
                p1 += fmaxf(acc[mf][nf][2] + Pe1[gc] + Pm1[gc], 0.f) * u0;
                p1 += fmaxf(acc[mf][nf][3] + Pe1[gc + 1] + Pm1[gc + 1], 0.f) * u1;
            }
            p0 += __shfl_xor_sync(0xffffffffu, p0, 1);
            p0 += __shfl_xor_sync(0xffffffffu, p0, 2);
            p1 += __shfl_xor_sync(0xffffffffu, p1, 1);
            p1 += __shfl_xor_sync(0xffffffffu, p1, 2);
            if ((lane & 3) == 0) {
                g_spart[(size_t)slot * MSr + r0] = p0;
                g_spart[(size_t)slot * MSr + r1] = p1;
            }
        }
    } else {
        #pragma unroll
        for (int mf = 0; mf < 2; mf++) {
            int rl0 = wm * 32 + mf * 16 + qrow;
            int j0 = m0 + rl0;
            int bc0 = s_rows[rl0] & (Bq - 1);
            int bc1 = s_rows[rl0 + 8] & (Bq - 1);
            const float* Pm0 = g_PmolW + (size_t)bc0 * Hh;
            const float* Pm1 = g_PmolW + (size_t)bc1 * Hh;
            #pragma unroll
            for (int nf = 0; nf < 8; nf++) {
                int col = n0 + wn * 64 + nf * 8 + qk;
                float v00 = fmaxf(acc[mf][nf][0] + Pm0[col], 0.f);
                float v01 = fmaxf(acc[mf][nf][1] + Pm0[col + 1], 0.f);
                float v10 = fmaxf(acc[mf][nf][2] + Pm1[col], 0.f);
                float v11 = fmaxf(acc[mf][nf][3] + Pm1[col + 1], 0.f);
                __nv_bfloat162 h2, l2;
                __nv_bfloat16 h, l;
                splitbf(v00, h, l); h2.x = h; l2.x = l;
                splitbf(v01, h, l); h2.y = h; l2.y = l;
                *(__nv_bfloat162*)&g_phid_hi[(size_t)(Bq + j0) * Hh + col] = h2;
                *(__nv_bfloat162*)&g_phid_lo[(size_t)(Bq + j0) * Hh + col] = l2;
                splitbf(v10, h, l); h2.x = h; l2.x = l;
                splitbf(v11, h, l); h2.y = h; l2.y = l;
                *(__nv_bfloat162*)&g_phid_hi[(size_t)(Bq + j0 + 8) * Hh + col] = h2;
                *(__nv_bfloat162*)&g_phid_lo[(size_t)(Bq + j0 + 8) * Hh + col] = l2;
            }
        }
    }
}

// logits GEMM with fused softmax partials. grid (8, MPRED/128)
__global__ __launch_bounds__(256)
void tc_gemm_logits(const float* __restrict__ bias,
                    const int* __restrict__ root_wid, const int* __restrict__ y_wid)
{
    extern __shared__ char smc[];
    const uint32_t sbase = smem_u32(smc);

    const int tid = threadIdx.x;
    const int wid_ = tid >> 5;
    const int lane = tid & 31;
    const int wm = wid_ & 3;
    const int wn = wid_ >> 2;
    const int qrow = lane >> 2;
    const int qk = (lane & 3) << 1;
    const int m0 = blockIdx.y * 128;
    const int n0 = blockIdx.x * 128;

    const int ar = tid >> 1;
    const int bo = (tid & 1) * 64;
    const char* AhiBase = (const char*)(g_phid_hi + (size_t)(m0 + ar) * Hh) + bo;
    const char* AloBase = (const char*)(g_phid_lo + (size_t)(m0 + ar) * Hh) + bo;
    const char* BhiBase = (const char*)(g_Bo_hi + (size_t)(n0 + ar) * Hh) + bo;
    const char* BloBase = (const char*)(g_Bo_lo + (size_t)(n0 + ar) * Hh) + bo;

    float acc[2][8][4];
    #pragma unroll
    for (int mf = 0; mf < 2; mf++)
        #pragma unroll
        for (int nf = 0; nf < 8; nf++)
            #pragma unroll
            for (int r = 0; r < 4; r++) acc[mf][nf][r] = 0.f;

    tc_main_sa(AhiBase, AloBase, BhiBase, BloBase, smc, sbase, tid, wm, wn, qrow, qk, acc);

    const int slot = blockIdx.x * 2 + wn;
    #pragma unroll
    for (int mf = 0; mf < 2; mf++) {
        #pragma unroll
        for (int half = 0; half < 2; half++) {
            int j = m0 + wm * 32 + mf * 16 + qrow + half * 8;
            int tgt = (j < Bq) ? root_wid[j] : y_wid[g_cmap[j - Bq]];
            float mv = -1e30f; int mi = 0;
            float vv[16];
            #pragma unroll
            for (int nf = 0; nf < 8; nf++) {
                int col = n0 + wn * 64 + nf * 8 + qk;
                float a = acc[mf][nf][half * 2 + 0] + bias[col];
                float b = acc[mf][nf][half * 2 + 1] + bias[col + 1];
                vv[nf * 2] = a; vv[nf * 2 + 1] = b;
                if (a > mv) { mv = a; mi = col; }
                if (b > mv) { mv = b; mi = col + 1; }
                if (col == tgt) g_tlog[j] = a;
                if (col + 1 == tgt) g_tlog[j] = b;
            }
            #pragma unroll
            for (int o = 1; o <= 2; o <<= 1) {
                float ov = __shfl_xor_sync(0xffffffffu, mv, o);
                int oi = __shfl_xor_sync(0xffffffffu, mi, o);
                if (ov > mv || (ov == mv && oi < mi)) { mv = ov; mi = oi; }
            }
            float s = 0.f;
            #pragma unroll
            for (int k = 0; k < 16; k++) s += __expf(vv[k] - mv);
            s += __shfl_xor_sync(0xffffffffu, s, 1);
            s += __shfl_xor_sync(0xffffffffu, s, 2);
            if ((lane & 3) == 0) {
                g_smax[(size_t)slot * MPRED + j] = mv;
                g_ssum[(size_t)slot * MPRED + j] = s;
                g_sargi[(size_t)slot * MPRED + j] = mi;
            }
        }
    }
}

// fused emb-precompute: 4 GEMMs selected by blockIdx.z
__global__ __launch_bounds__(256)
void tc_gemm_pre4(const float* __restrict__ A,
                  const __nv_bfloat16* b0h, const __nv_bfloat16* b0l,
                  const float* bias0, float* C0,
                  const __nv_bfloat16* b1h, const __nv_bfloat16* b1l,
                  const float* bias1, float* C1,
                  const __nv_bfloat16* b2h, const __nv_bfloat16* b2l,
                  const float* bias2, float* C2,
                  const __nv_bfloat16* b3h, const __nv_bfloat16* b3l,
                  const float* bias3, float* C3)
{
    extern __shared__ char smc[];
    const uint32_t sbase = smem_u32(smc);
    const int z = blockIdx.z;
    const __nv_bfloat16* Bhi = (z == 0) ? b0h : (z == 1) ? b1h : (z == 2) ? b2h : b3h;
    const __nv_bfloat16* Blo = (z == 0) ? b0l : (z == 1) ? b1l : (z == 2) ? b2l : b3l;
    const float* bias = (z == 0) ? bias0 : (z == 1) ? bias1 : (z == 2) ? bias2 : bias3;
    float* C = (z == 0) ? C0 : (z == 1) ? C1 : (z == 2) ? C2 : C3;

    const int tid = threadIdx.x;
    const int wid_ = tid >> 5;
    const int lane = tid & 31;
    const int wm = wid_ & 3;
    const int wn = wid_ >> 2;
    const int qrow = lane >> 2;
    const int qk = (lane & 3) << 1;
    const int m0 = blockIdx.y * 128;
    const int n0 = blockIdx.x * 128;

    const int ar = tid >> 1;
    const int ac = (tid & 1) * 32;
    const int bo = (tid & 1) * 64;
    const float* Abase = A + (size_t)(m0 + ar) * Hh + ac;
    const char* BhiBase = (const char*)(Bhi + (size_t)(n0 + ar) * Hh) + bo;
    const char* BloBase = (const char*)(Blo + (size_t)(n0 + ar) * Hh) + bo;

    float acc[2][8][4];
    #pragma unroll
    for (int mf = 0; mf < 2; mf++)
        #pragma unroll
        for (int nf = 0; nf < 8; nf++)
            #pragma unroll
            for (int r = 0; r < 4; r++) acc[mf][nf][r] = 0.f;

    tc_main(Abase, BhiBase, BloBase, smc, sbase, tid, wm, wn, qrow, qk, acc);

    #pragma unroll
    for (int mf = 0; mf < 2; mf++) {
        int r0 = m0 + wm * 32 + mf * 16 + qrow;
        #pragma unroll
        for (int nf = 0; nf < 8; nf++) {
            int col = n0 + wn * 64 + nf * 8 + qk;
            float2 o0 = {acc[mf][nf][0] + bias[col], acc[mf][nf][1] + bias[col + 1]};
            float2 o1 = {acc[mf][nf][2] + bias[col], acc[mf][nf][3] + bias[col + 1]};
            *(float2*)&C[(size_t)r0 * Hh + col] = o0;
            *(float2*)&C[(size_t)(r0 + 8) * Hh + col] = o1;
        }
    }
}

// ---------------- housekeeping ----------------
__global__ __launch_bounds__(256)
void prep_kernel()
{
    int i = blockIdx.x * 256 + threadIdx.x;
    if (i < 5) g_acc[i] = 0.0;
    if (i == 5) { g_barc = 0; g_ccount = 0; }
    if (i < Hh) {
        g_hbuf[(size_t)PADROW * Hh + i] = 0.f;
        g_hbufUr[(size_t)PADROW * Hh + i] = 0.f;
        g_hbuf_hi[(size_t)PADROW * Hh + i] = __float2bfloat16(0.f);
        g_hbuf_lo[(size_t)PADROW * Hh + i] = __float2bfloat16(0.f);
    }
    if (i < NCMP + 256) g_cmap[i] = 0;
}

__global__ __launch_bounds__(256)
void compact_kernel(const int* __restrict__ dirs)
{
    int i = blockIdx.x * 256 + threadIdx.x;
    if (dirs[i]) {
        int s = atomicAdd(&g_ccount, 1);
        g_cmap[s] = i;
    }
}

// build_curo + phid0 merged (blocks >= MSr do phid0 rows)
__global__ __launch_bounds__(256)
void build_curo(const int* __restrict__ oni, const int* __restrict__ roni)
{
    int i = blockIdx.x, tid = threadIdx.x;
    if (i >= MSr) {
        int b = i - MSr;
        for (int h2 = tid * 2; h2 < Hh; h2 += 512) {
            float v0 = fmaxf(g_PmolW[(size_t)b * Hh + h2], 0.f);
            float v1 = fmaxf(g_PmolW[(size_t)b * Hh + h2 + 1], 0.f);
            __nv_bfloat162 h2v, l2v;
            __nv_bfloat16 h, l;
            splitbf(v0, h, l); h2v.x = h; l2v.x = l;
            splitbf(v1, h, l); h2v.y = h; l2v.y = l;
            *(__nv_bfloat162*)&g_phid_hi[(size_t)b * Hh + h2] = h2v;
            *(__nv_bfloat162*)&g_phid_lo[(size_t)b * Hh + h2] = l2v;
        }
        return;
    }
    __shared__ int ids[MAXNB];
    if (tid < MAXNB)
        ids[tid] = (i < TBq) ? oni[(size_t)i * MAXNB + tid]
                             : roni[(size_t)(i - TBq) * MAXNB + tid];
    __syncthreads();
    for (int h4 = tid * 4; h4 < Hh; h4 += 1024) {
        float4 v = {0.f, 0.f, 0.f, 0.f};
        #pragma unroll
        for (int n = 0; n < MAXNB; n++) {
            int id = ids[n];
            if (id == PADROW) continue;
            float4 hv = *(const float4*)&g_hbuf[(size_t)id * Hh + h4];
            v.x += hv.x; v.y += hv.y; v.z += hv.z; v.w += hv.w;
        }
        uint2 lo, hi;
        hi = pack_hi4(v.x, v.y, v.z, v.w, lo);
        *(uint2*)&g_curo_hi[(size_t)i * Hh + h4] = hi;
        *(uint2*)&g_curo_lo[(size_t)i * Hh + h4] = lo;
    }
}

// ---------------- stop head finalize ----------------
__global__ __launch_bounds__(256)
void stop_final_kernel(const float* __restrict__ bs, const int* __restrict__ dirs)
{
    int i = blockIdx.x * 256 + threadIdx.x;
    float s = bs[0];
    #pragma unroll
    for (int k = 0; k < 8; k++) s += g_spart[(size_t)k * MSr + i];
    float tgt = (i < TBq) ? (float)dirs[i] : 0.f;
    float loss = fmaxf(s, 0.f) - s * tgt + log1pf(expf(-fabsf(s)));
    float corr = ((s >= 0.5f) == (tgt > 0.5f)) ? 1.f : 0.f;
    __shared__ double r0[256], r1[256];
    int tid = threadIdx.x;
    r0[tid] = (double)loss;
    r1[tid] = (double)corr;
    __syncthreads();
    for (int o = 128; o > 0; o >>= 1) {
        if (tid < o) { r0[tid] += r0[tid + o]; r1[tid] += r1[tid + o]; }
        __syncthreads();
    }
    if (tid == 0) {
        atomicAdd(&g_acc[0], r0[0]);
        atomicAdd(&g_acc[1], r1[0]);
    }
}

// ---------------- pred finalize: combine softmax partials ----------------
__global__ __launch_bounds__(256)
void pred_final_kernel(const int* __restrict__ root_wid, const int* __restrict__ y_wid)
{
    int j = blockIdx.x * 256 + threadIdx.x;
    int tgt = (j < Bq) ? root_wid[j] : y_wid[g_cmap[j - Bq]];
    float gm = -1e30f; int gi = 0;
    #pragma unroll
    for (int s = 0; s < 16; s++) {
        float mv = g_smax[(size_t)s * MPRED + j];
        int mi = g_sargi[(size_t)s * MPRED + j];
        if (mv > gm) { gm = mv; gi = mi; }
    }
    float sum = 0.f;
    #pragma unroll
    for (int s = 0; s < 16; s++)
        sum += g_ssum[(size_t)s * MPRED + j] * __expf(g_smax[(size_t)s * MPRED + j] - gm);
    float lse = gm + logf(sum);
    float ce = -(g_tlog[j] - lse);
    float corr = (gi == tgt) ? 1.f : 0.f;

    __shared__ double r0[256], r1[256];
    int tid = threadIdx.x;
    r0[tid] = (double)ce;
    r1[tid] = (double)corr;
    __syncthreads();
    for (int o = 128; o > 0; o >>= 1) {
        if (tid < o) { r0[tid] += r0[tid + o]; r1[tid] += r1[tid + o]; }
        __syncthreads();
    }
    if (tid == 0) {
        atomicAdd(&g_acc[2], r0[0]);
        atomicAdd(&g_acc[3], r1[0]);
        atomicAdd(&g_acc[4], 256.0);
    }
}

__global__ void finalize_kernel(float* out)
{
    out[0] = (float)(g_acc[2] / (double)Bq);
    out[1] = (float)(g_acc[0] / (double)Bq);
    out[2] = (float)(g_acc[3] / g_acc[4]);
    out[3] = (float)(g_acc[1] / (double)MSr);
}

// ---------------- launch ----------------
extern "C" void kernel_launch(void* const* d_in, const int* in_sizes, int n_in,
                              void* d_out, int out_size)
{
    const float* mol_vec  = (const float*)d_in[0];
    const int*   wid      = (const int*)d_in[1];
    const int*   y_wid    = (const int*)d_in[2];
    const int*   dirs     = (const int*)d_in[3];
    const int*   hni      = (const int*)d_in[4];
    const int*   oni      = (const int*)d_in[5];
    const int*   root_wid = (const int*)d_in[6];
    const int*   roni     = (const int*)d_in[7];
    const float* emb      = (const float*)d_in[8];
    const float* Wz       = (const float*)d_in[9];
    const float* bz       = (const float*)d_in[10];
    const float* Wr       = (const float*)d_in[11];
    const float* br       = (const float*)d_in[12];
    const float* Ur       = (const float*)d_in[13];
    const float* Wh       = (const float*)d_in[14];
    const float* bh       = (const float*)d_in[15];
    const float* Wm       = (const float*)d_in[16];
    const float* bW       = (const float*)d_in[17];
    const float* U        = (const float*)d_in[18];
    const float* bU       = (const float*)d_in[19];
    const float* Wo       = (const float*)d_in[20];
    const float* bo       = (const float*)d_in[21];
    const float* Us       = (const float*)d_in[22];
    const float* bs       = (const float*)d_in[23];

    float *gPz, *gPr, *gPh, *gPembU, *gPmolU, *gPmolW;
    __nv_bfloat16 *gBuH, *gBuL, *gBwH, *gBwL, *gBoH, *gBoL;
    __nv_bfloat16 *gBzhH, *gBzhL, *gBUrH, *gBUrL;
    __nv_bfloat16 *gBz0H, *gBz0L, *gBr0H, *gBr0L, *gBh0H, *gBh0L, *gBU0H, *gBU0L;
    cudaGetSymbolAddress((void**)&gPz, g_Pz);
    cudaGetSymbolAddress((void**)&gPr, g_Pr);
    cudaGetSymbolAddress((void**)&gPh, g_Ph);
    cudaGetSymbolAddress((void**)&gPembU, g_PembU);
    cudaGetSymbolAddress((void**)&gPmolU, g_PmolU);
    cudaGetSymbolAddress((void**)&gPmolW, g_PmolW);
    cudaGetSymbolAddress((void**)&gBuH, g_Bu_hi);
    cudaGetSymbolAddress((void**)&gBuL, g_Bu_lo);
    cudaGetSymbolAddress((void**)&gBwH, g_Bw_hi);
    cudaGetSymbolAddress((void**)&gBwL, g_Bw_lo);
    cudaGetSymbolAddress((void**)&gBoH, g_Bo_hi);
    cudaGetSymbolAddress((void**)&gBoL, g_Bo_lo);
    cudaGetSymbolAddress((void**)&gBzhH, g_Bzh_hi);
    cudaGetSymbolAddress((void**)&gBzhL, g_Bzh_lo);
    cudaGetSymbolAddress((void**)&gBUrH, g_BUr_hi);
    cudaGetSymbolAddress((void**)&gBUrL, g_BUr_lo);
    cudaGetSymbolAddress((void**)&gBz0H, g_Bz0_hi);
    cudaGetSymbolAddress((void**)&gBz0L, g_Bz0_lo);
    cudaGetSymbolAddress((void**)&gBr0H, g_Br0_hi);
    cudaGetSymbolAddress((void**)&gBr0L, g_Br0_lo);
    cudaGetSymbolAddress((void**)&gBh0H, g_Bh0_hi);
    cudaGetSymbolAddress((void**)&gBh0L, g_Bh0_lo);
    cudaGetSymbolAddress((void**)&gBU0H, g_BU0_hi);
    cudaGetSymbolAddress((void**)&gBU0L, g_BU0_lo);

    cudaFuncSetAttribute(tc_gemm_post,
                         cudaFuncAttributeMaxDynamicSharedMemorySize, TCSM_BYTES);
    cudaFuncSetAttribute(tc_gemm_logits,
                         cudaFuncAttributeMaxDynamicSharedMemorySize, TCSM_BYTES);
    cudaFuncSetAttribute(tc_gemm_pre4,
                         cudaFuncAttributeMaxDynamicSharedMemorySize, TCSM_BYTES);
    cudaFuncSetAttribute(scan_kernel,
                         cudaFuncAttributeMaxDynamicSharedMemorySize, SCAN_SMEM);

    prep_kernel<<<47, 256>>>();
    compact_kernel<<<92, 256>>>(dirs);

    ConvJobs jobs;
    jobs.j[0] = {U + (size_t)Hh * Hh, gBuH, gBuL, 16};
    jobs.j[1] = {Wm, gBwH, gBwL, 16};
    jobs.j[2] = {Wo, gBoH, gBoL, 32};
    jobs.j[3] = {Wz + (size_t)Hh * Hh, gBzhH, gBzhL, 16};
    jobs.j[4] = {Wh + (size_t)Hh * Hh, gBzhH + (size_t)Hh * Hh, gBzhL + (size_t)Hh * Hh, 16};
    jobs.j[5] = {Ur, gBUrH, gBUrL, 16};
    jobs.j[6] = {Wz, gBz0H, gBz0L, 16};
    jobs.j[7] = {Wr, gBr0H, gBr0L, 16};
    jobs.j[8] = {Wh, gBh0H, gBh0L, 16};
    jobs.j[9] = {U, gBU0H, gBU0L, 16};
    convT_all<<<dim3(32, 16, 10), 256>>>(jobs);

    tc_gemm_pre4<<<dim3(4, 8, 4), 256, TCSM_BYTES>>>(
        emb,
        gBz0H, gBz0L, bz, gPz,
        gBr0H, gBr0L, br, gPr,
        gBh0H, gBh0L, bh, gPh,
        gBU0H, gBU0L, bU, gPembU);
    sgemm_kernel<<<dim3(Hh / BN, Bq / BM), 256>>>(Bq, Hh, Ll, mol_vec, U + (size_t)2 * Hh * Hh, nullptr, gPmolU);
    sgemm_kernel<<<dim3(Hh / BN, Bq / BM), 256>>>(Bq, Hh, Ll, mol_vec, Wm + (size_t)Hh * Hh, bW, gPmolW);

    // persistent fused GRU scan
    scan_kernel<<<NBLK, 256, SCAN_SMEM>>>(wid, hni);

    // gathers (curo + phid rows 0..511)
    build_curo<<<MSr + Bq, 256>>>(oni, roni);

    // merged stop + phid GEMMs
    tc_gemm_post<<<dim3(4, STOPY + PHIDY), 256, TCSM_BYTES>>>(wid, root_wid, Us);
    stop_final_kernel<<<94, 256>>>(bs, dirs);

    // logits GEMM with fused softmax partials, then tiny finalize
    tc_gemm_logits<<<dim3(8, MPRED / 128), 256, TCSM_BYTES>>>(bo, root_wid, y_wid);
    pred_final_kernel<<<48, 256>>>(root_wid, y_wid);

    finalize_kernel<<<1, 1>>>((float*)d_out);
}